// round 13
// baseline (speedup 1.0000x reference)
#include <cuda_runtime.h>
#include <math.h>

#define N_NODES 2048
#define C_DIM   256
#define H_DIM   8
#define DQK_DIM 32
#define CV_DIM  16
#define K_DIM   8
#define U_DIM   25
#define F_DIM   400           // 2*K*U : cos block then sin block
#define X_DIM   36864         // H * DQK * CV * 9
#define XH_DIM  4608          // per-h slab of X

// ---------------- scratch (static __device__, no allocation) ----------------
__device__ float  d_qfT  [256 * N_NODES];
__device__ float  d_kfT  [256 * N_NODES];
__device__ float  d_vT   [1152 * N_NODES];
__device__ float  d_PhiT [F_DIM * N_NODES];
__device__ float  d_kfsum[256];
__device__ float  d_Z    [N_NODES * H_DIM];
__device__ float  d_Mbuf [(size_t)F_DIM * X_DIM];
__device__ float  d_Bbuf [(size_t)F_DIM * X_DIM];
__device__ float  d_accb [(size_t)N_NODES * 9 * 128];
__device__ float  d_G    [K_DIM * U_DIM * H_DIM * 81];
__device__ float  d_YW   [9 * U_DIM];
__device__ double d_Rs   [729];
__device__ float  d_RRED [729];
__device__ float  d_DIRS [U_DIM * 3];

__device__ __constant__ double c_fact[9] =
    {1.,1.,2.,6.,24.,120.,720.,5040.,40320.};

// ---------------- packed f32x2 helpers ---------------------------------------
__device__ __forceinline__ unsigned long long dup2(float a){
    unsigned long long r;
    asm("mov.b64 %0, {%1, %1};" : "=l"(r) : "f"(a));
    return r;
}
__device__ __forceinline__ void fma2(unsigned long long& d,
                                     unsigned long long a,
                                     unsigned long long b){
    asm("fma.rn.f32x2 %0, %1, %2, %0;" : "+l"(d) : "l"(a), "l"(b));
}
__device__ __forceinline__ float2 unpk(unsigned long long v){
    float2 r;
    asm("mov.b64 {%0, %1}, %2;" : "=f"(r.x), "=f"(r.y) : "l"(v));
    return r;
}

// ---------------- Clebsch-Gordan machinery (fp64, matches numpy) ------------
__device__ double cg_coef(int j1,int m1,int j2,int m2,int j,int m){
    if (m1 + m2 != m) return 0.0;
    int dj = j1 - j2; if (dj < 0) dj = -dj;
    if (j < dj || j > j1 + j2) return 0.0;
    double pref = sqrt((2.0*j+1.0) * c_fact[j+j1-j2] * c_fact[j-j1+j2] *
                       c_fact[j1+j2-j] / c_fact[j1+j2+j+1]);
    pref *= sqrt(c_fact[j+m]*c_fact[j-m]*c_fact[j1-m1]*c_fact[j1+m1]*
                 c_fact[j2-m2]*c_fact[j2+m2]);
    double s = 0.0;
    for (int k = 0; k <= j1 + j2 - j; k++){
        int d1=j1+j2-j-k, d2=j1-m1-k, d3=j2+m2-k, d4=j-j2+m1+k, d5=j-j1-m2+k;
        if (d1 < 0 || d2 < 0 || d3 < 0 || d4 < 0 || d5 < 0) continue;
        double term = 1.0/(c_fact[k]*c_fact[d1]*c_fact[d2]*c_fact[d3]*
                           c_fact[d4]*c_fact[d5]);
        s += (k & 1) ? -term : term;
    }
    return pref * s;
}

__device__ void umat_fill(int l, double* ur, double* ui){
    int n = 2*l + 1;
    for (int i = 0; i < n*n; i++){ ur[i] = 0.0; ui[i] = 0.0; }
    double s = 1.0 / sqrt(2.0);
    for (int m = -l; m <= l; m++){
        if (m > 0){
            ur[(l+m)*n + (l+m)] = (m & 1) ? -s : s;
            ur[(l+m)*n + (l-m)] = s;
        } else if (m == 0){
            ur[l*n + l] = 1.0;
        } else {
            int am = -m;
            ui[(l+m)*n + (l+m)] = s;
            ui[(l+m)*n + (l-m)] = (am & 1) ? s : -s;   // -(-1)^m * s
        }
    }
}

// ---------------- sphere grid + YW + zero d_Rs -------------------------------
__global__ void k_sphere(){
    const double PI = 3.14159265358979323846264338327950288;
    int tid = threadIdx.x;
    for (int i = tid; i < 729; i += blockDim.x) d_Rs[i] = 0.0;
    __shared__ double gx[5], gw[5];
    if (tid == 0){
        double x1 = sqrt(5.0 - 2.0*sqrt(10.0/7.0))/3.0;
        double x2 = sqrt(5.0 + 2.0*sqrt(10.0/7.0))/3.0;
        double w0 = 128.0/225.0;
        double w1 = (322.0 + 13.0*sqrt(70.0))/900.0;
        double w2 = (322.0 - 13.0*sqrt(70.0))/900.0;
        gx[0]=-x2; gx[1]=-x1; gx[2]=0.0; gx[3]=x1; gx[4]=x2;
        gw[0]=w2;  gw[1]=w1;  gw[2]=w0;  gw[3]=w1;  gw[4]=w2;
    }
    __syncthreads();
    if (tid < U_DIM){
        int ith = tid / 5, iph = tid % 5;
        double ct = gx[ith];
        double w  = gw[ith] * (2.0*PI/5.0);
        double ph = 2.0*PI*iph/5.0;
        double st = sqrt(fmax(1.0 - ct*ct, 0.0));
        double x = st*cos(ph), y = st*sin(ph), z = ct;
        d_DIRS[tid*3+0] = (float)x;
        d_DIRS[tid*3+1] = (float)y;
        d_DIRS[tid*3+2] = (float)z;
        double Y[9];
        Y[0]=0.282095; Y[1]=0.488603*y; Y[2]=0.488603*z; Y[3]=0.488603*x;
        Y[4]=1.092548*x*y; Y[5]=1.092548*y*z; Y[6]=0.315392*(3.0*z*z-1.0);
        Y[7]=1.092548*x*z; Y[8]=0.546274*(x*x-y*y);
        for (int e=0;e<9;e++) d_YW[e*U_DIM+tid] = (float)(Y[e]*w);
    }
}

// ---------------- CG: one (l1,l2,L) combo per block --------------------------
__global__ void k_cg(){
    __shared__ double cgc[125], rr[125], ri[125];
    __shared__ double U1r[25],U1i[25],U2r[25],U2i[25],U3r[25],U3i[25];
    __shared__ double nrm[2];
    const int l1s[15] = {0,0,0,1,1,1,1,1,1,2,2,2,2,2,2};
    const int l2s[15] = {0,1,2,0,1,1,1,2,2,0,1,1,2,2,2};
    const int Lss[15] = {0,1,2,1,0,1,2,1,2,2,1,2,0,1,2};
    const int off[3]  = {0,1,4};
    int b = blockIdx.x;
    int l1 = l1s[b], l2 = l2s[b], L = Lss[b];
    int tid = threadIdx.x;
    int n1 = 2*l1+1, n2 = 2*l2+1, n3 = 2*L+1;
    int tot = n1*n2*n3;
    for (int i=tid;i<tot;i+=blockDim.x){
        int i1=i/(n2*n3), i2=(i/n3)%n2, i3=i%n3;
        cgc[i] = cg_coef(l1, i1-l1, l2, i2-l2, L, i3-L);
    }
    if (tid==0){
        umat_fill(l1,U1r,U1i); umat_fill(l2,U2r,U2i); umat_fill(L,U3r,U3i);
        nrm[0]=0.0; nrm[1]=0.0;
    }
    __syncthreads();
    for (int i=tid;i<tot;i+=blockDim.x){
        int a=i/(n2*n3), bb=(i/n3)%n2, c=i%n3;
        double sr=0.0, si=0.0;
        for (int u=0;u<n1;u++)
        for (int v=0;v<n2;v++)
        for (int w=0;w<n3;w++){
            double cg = cgc[(u*n2+v)*n3+w];
            if (cg == 0.0) continue;
            double ar=U1r[a*n1+u], ai=U1i[a*n1+u];
            double br=U2r[bb*n2+v], bi=U2i[bb*n2+v];
            double cr=U3r[c*n3+w], ci=-U3i[c*n3+w];
            double pr=ar*br-ai*bi, pi=ar*bi+ai*br;
            sr += (pr*cr - pi*ci)*cg;
            si += (pr*ci + pi*cr)*cg;
        }
        rr[i]=sr; ri[i]=si;
        atomicAdd(&nrm[0], sr*sr);
        atomicAdd(&nrm[1], si*si);
    }
    __syncthreads();
    bool useRe = (nrm[0] >= nrm[1]);
    for (int i=tid;i<tot;i+=blockDim.x){
        int a=i/(n2*n3), bb=(i/n3)%n2, c=i%n3;
        double val = useRe ? rr[i] : ri[i];
        d_Rs[(off[l1]+a)*81 + (off[l2]+bb)*9 + (off[L]+c)] = val;
    }
}

// ---------------- RRED finalize ----------------------------------------------
__global__ void k_rred(){
    int i = blockIdx.x*blockDim.x + threadIdx.x;
    if (i >= 729) return;
    int m = i % 9;
    double cnt = (m==0) ? 3.0 : 6.0;
    d_RRED[i] = (float)(d_Rs[i]/cnt);
}

// ---------------- G[k,u,h,l,m] = sum_e YW[e,u]*a[ldeg(e),h,k]*RRED[e,l,m] ----
__global__ void k_G(const float* __restrict__ a){
    int idx = blockIdx.x*blockDim.x + threadIdx.x;
    if (idx >= K_DIM*U_DIM*H_DIM*81) return;
    int m = idx % 9, l = (idx/9)%9, h = (idx/81)%8, u = (idx/648)%25, k = idx/16200;
    const int ldeg[9] = {0,1,1,1,2,2,2,2,2};
    float s = 0.f;
    #pragma unroll
    for (int e=0;e<9;e++)
        s += d_YW[e*25+u] * a[ldeg[e]*64 + h*8 + k] * d_RRED[e*81 + l*9 + m];
    d_G[idx] = s;
}

// ---------------- per-node features (2 nodes / block) ------------------------
#define NPB 2
__global__ void k_features(const float* __restrict__ pos,
                           const float* __restrict__ feat,
                           const float* __restrict__ Wq,
                           const float* __restrict__ Wk,
                           const float* __restrict__ Wv,
                           const float* __restrict__ kappa){
    __shared__ float sf  [NPB][2304];
    __shared__ float s123[NPB][768];
    __shared__ float spos[NPB][3];
    __shared__ float skap[8];
    int tid = threadIdx.x;
    int n0  = blockIdx.x * NPB;
    if (tid < NPB*3) spos[tid/3][tid%3] = pos[n0*3 + tid];
    if (tid < 8) skap[tid] = kappa[tid];
    for (int nb=0; nb<NPB; nb++)
        for (int i=tid; i<2304; i+=256)
            sf[nb][i] = feat[(size_t)(n0+nb)*2304 + i];
    __syncthreads();
    for (int i=tid; i<NPB*256; i+=256){
        int nb = i/256, c = i%256;
        const float* f = sf[nb];
        s123[nb][c] = f[c];
        s123[nb][256+c] = sqrtf(f[256+c]*f[256+c] + f[512+c]*f[512+c] +
                                f[768+c]*f[768+c] + 1e-8f);
        float s = 1e-8f;
        #pragma unroll
        for (int m=4;m<9;m++){ float t = f[m*256+c]; s += t*t; }
        s123[nb][512+c] = sqrtf(s);
    }
    __syncthreads();

    // q,k projections: thread = output column j (0..255)
    {
        float qa[NPB] = {0,0}, ka[NPB] = {0,0};
        int j = tid;
        for (int g=0; g<3; g++){
            const float* wqb = Wq + g*65536 + j;
            const float* wkb = Wk + g*65536 + j;
            #pragma unroll 4
            for (int c=0;c<256;c++){
                float wq = wqb[c*256];
                float wk = wkb[c*256];
                #pragma unroll
                for (int nb=0;nb<NPB;nb++){
                    float s = s123[nb][g*256+c];
                    qa[nb] += s*wq; ka[nb] += s*wk;
                }
            }
        }
        #pragma unroll
        for (int nb=0;nb<NPB;nb++){
            int n = n0+nb;
            float q = qa[nb], k = ka[nb];
            float qf = (q > 0.f) ? q + 1.f : expf(q);
            float kf = (k > 0.f) ? k + 1.f : expf(k);
            d_qfT[(size_t)j*N_NODES + n] = qf;
            d_kfT[(size_t)j*N_NODES + n] = kf;
        }
    }

    // v: jv = h*16+c (0..127), one node per half-block
    {
        int jv = tid & 127, nb = tid >> 7;
        float acc[9];
        #pragma unroll
        for (int l=0;l<9;l++) acc[l] = 0.f;
        #pragma unroll 4
        for (int ch=0; ch<256; ch++){
            float w = Wv[ch*128 + jv];
            #pragma unroll
            for (int l=0;l<9;l++) acc[l] += sf[nb][l*256+ch]*w;
        }
        #pragma unroll
        for (int l=0;l<9;l++)
            d_vT[(size_t)(jv*9+l)*N_NODES + (n0+nb)] = acc[l];
    }

    // Phi
    for (int i=tid; i<NPB*200; i+=256){
        int nb = i/200, r = i%200;
        int k = r/25, u = r%25;
        float dot = spos[nb][0]*d_DIRS[u*3+0] + spos[nb][1]*d_DIRS[u*3+1] +
                    spos[nb][2]*d_DIRS[u*3+2];
        float ph = skap[k]*dot;
        float c, s;
        sincosf(ph, &s, &c);
        d_PhiT[(size_t)r      *N_NODES + n0+nb] = c;
        d_PhiT[(size_t)(200+r)*N_NODES + n0+nb] = s;
    }
}

// ---------------- kfsum + Z --------------------------------------------------
__global__ void k_ksum(){
    int j = blockIdx.x;
    int tid = threadIdx.x;
    float s = 0.f;
    for (int n=tid; n<N_NODES; n+=256) s += d_kfT[(size_t)j*N_NODES + n];
    #pragma unroll
    for (int o=16;o;o>>=1) s += __shfl_xor_sync(0xffffffffu, s, o);
    __shared__ float red[8];
    if ((tid & 31) == 0) red[tid>>5] = s;
    __syncthreads();
    if (tid == 0){
        float t = 0.f;
        #pragma unroll
        for (int w=0;w<8;w++) t += red[w];
        d_kfsum[j] = t;
    }
}

__global__ void k_Z(){
    int idx = blockIdx.x*blockDim.x + threadIdx.x;
    if (idx >= N_NODES*H_DIM) return;
    int n = idx % N_NODES, h = idx / N_NODES;
    float s = 0.f;
    #pragma unroll
    for (int d=0; d<32; d++)
        s += d_qfT[(size_t)(h*32+d)*N_NODES + n] * d_kfsum[h*32+d];
    d_Z[idx] = s + 1e-6f;
}

// ---------------- key GEMM: M[f,x] = sum_n Phi[f,n]*kf[hd(x),n]*v[hcl(x),n] --
// R6 champion kernel, unchanged
#define KG_AST 68
#define KG_BST 132
__global__ void __launch_bounds__(128,3) k_keygemm(){
    __shared__ float As[16*KG_AST];
    __shared__ float Bs[16*KG_BST];
    int tid = threadIdx.x;
    int x0 = blockIdx.x * 128;
    int f0 = blockIdx.y * 64;
    int wid = tid>>5, lane = tid&31;
    int wf = wid>>1, wx = wid&1;      // warp grid 2f x 2x
    int tf = lane&3, tx = lane>>2;    // thread grid 4f x 8x
    int fr = tid&15, fcg = tid>>4;    // fill: n-row 0..15, col group 0..7

    unsigned kfo[16], vo[16];
    #pragma unroll
    for (int q=0;q<16;q++){
        int x = x0 + fcg + q*8;
        int h = x / XH_DIM, rem = x - h*XH_DIM;
        int d = rem / 144, cl = rem - d*144;
        kfo[q] = (unsigned)(h*32+d)*N_NODES;
        vo[q]  = (unsigned)(h*144+cl)*N_NODES;
    }
    unsigned long long acc[8][4];
    #pragma unroll
    for (int i=0;i<8;i++)
        #pragma unroll
        for (int j=0;j<4;j++) acc[i][j] = 0ull;

    for (int nb=0; nb<N_NODES; nb+=16){
        #pragma unroll
        for (int q=0;q<8;q++){
            int col = fcg + q*8;
            int f = f0 + col;
            As[fr*KG_AST + col] = (f < F_DIM) ? d_PhiT[(size_t)f*N_NODES + nb + fr] : 0.f;
        }
        #pragma unroll
        for (int q=0;q<16;q++){
            int col = fcg + q*8;
            Bs[fr*KG_BST + col] = d_kfT[kfo[q] + nb + fr] * d_vT[vo[q] + nb + fr];
        }
        __syncthreads();
        #pragma unroll
        for (int kk=0;kk<16;kk++){
            const float* ar = &As[kk*KG_AST + wf*32 + tf*8];
            float4 a0 = *(const float4*)ar;
            float4 a1 = *(const float4*)(ar+4);
            unsigned long long ad[8];
            ad[0]=dup2(a0.x); ad[1]=dup2(a0.y); ad[2]=dup2(a0.z); ad[3]=dup2(a0.w);
            ad[4]=dup2(a1.x); ad[5]=dup2(a1.y); ad[6]=dup2(a1.z); ad[7]=dup2(a1.w);
            const float* br = &Bs[kk*KG_BST + wx*64 + tx*8];
            ulonglong2 b01 = *(const ulonglong2*)br;
            ulonglong2 b23 = *(const ulonglong2*)(br+4);
            #pragma unroll
            for (int i=0;i<8;i++){
                fma2(acc[i][0], ad[i], b01.x);
                fma2(acc[i][1], ad[i], b01.y);
                fma2(acc[i][2], ad[i], b23.x);
                fma2(acc[i][3], ad[i], b23.y);
            }
        }
        __syncthreads();
    }
    #pragma unroll
    for (int i=0;i<8;i++){
        int f = f0 + wf*32 + tf*8 + i;
        if (f >= F_DIM) continue;
        float* mrow = d_Mbuf + (size_t)f*X_DIM + x0 + wx*64 + tx*8;
        ulonglong2 s0; s0.x = acc[i][0]; s0.y = acc[i][1];
        ulonglong2 s1; s1.x = acc[i][2]; s1.y = acc[i][3];
        *(ulonglong2*)&mrow[0] = s0;
        *(ulonglong2*)&mrow[4] = s1;
    }
}

// ---------------- fold: B[f,h,d,c,m] = sum_l M[f,h,d,c,l]*G[k,u,h,l,m] -------
__global__ void k_fold(){
    int idx = blockIdx.x*blockDim.x + threadIdx.x;
    if (idx >= F_DIM*4096) return;
    int c = idx % 16, d = (idx/16)%32, h = (idx/512)%8, f = idx/4096;
    int k = (f % 200) / 25, u = f % 25;
    const float* g = d_G + (size_t)((k*25+u)*8 + h)*81;
    size_t base = (size_t)f*X_DIM + h*XH_DIM + d*144 + c*9;
    float mrow[9];
    #pragma unroll
    for (int l=0;l<9;l++) mrow[l] = d_Mbuf[base+l];
    #pragma unroll
    for (int m=0;m<9;m++){
        float s = 0.f;
        #pragma unroll
        for (int l=0;l<9;l++) s += mrow[l]*g[l*9+m];
        d_Bbuf[base+m] = s;
    }
}

// ---------------- query GEMM: acc[n,cm] = sum_{f,d} Phi*qf*B ------------------
// R6 structure; B stored DUPLICATED in smem (conflict-free stride 100),
// inner loop: 5 LDS.128 + 24 FMA2, zero MOVs
#define QG_AST  132
#define QG_BDUP 100
__global__ void __launch_bounds__(128,3) k_querygemm(){
    __shared__ __align__(16) float As[16*QG_AST];
    __shared__ __align__(16) float Bq[16*QG_BDUP];
    int tid = threadIdx.x;
    int cm0 = blockIdx.x * 48;
    int n0  = blockIdx.y * 128;
    int h   = blockIdx.z;
    int wid = tid>>5, lane = tid&31;
    int wn = wid>>1, wc = wid&1;      // warp grid 2n x 2cm
    int tn = lane>>2, tx = lane&3;    // thread grid 8n x 4cm
    int brow = tid>>3;                // B fill: row 0..15
    int bcol0 = (tid&7)*6;            // B fill: 6 cols per thread

    float qreg[32];
    #pragma unroll
    for (int d=0;d<32;d++)
        qreg[d] = d_qfT[(size_t)(h*32+d)*N_NODES + n0 + tid];

    unsigned long long acc[4][6];
    #pragma unroll
    for (int i=0;i<4;i++)
        #pragma unroll
        for (int j=0;j<6;j++) acc[i][j] = 0ull;

    for (int f=0; f<F_DIM; f++){
        float ph = d_PhiT[(size_t)f*N_NODES + n0 + tid];
        const float* bb = d_Bbuf + (size_t)f*X_DIM + h*XH_DIM + cm0;
        #pragma unroll
        for (int hb=0; hb<2; hb++){
            #pragma unroll
            for (int dl=0; dl<16; dl++)
                As[dl*QG_AST + tid] = ph * qreg[hb*16 + dl];
            // B fill, duplicated pairs
            #pragma unroll
            for (int j=0;j<3;j++){
                float2 p = *(const float2*)&bb[(hb*16 + brow)*144 + bcol0 + j*2];
                *(float2*)&Bq[brow*QG_BDUP + (bcol0 + j*2)*2]     = make_float2(p.x, p.x);
                *(float2*)&Bq[brow*QG_BDUP + (bcol0 + j*2)*2 + 2] = make_float2(p.y, p.y);
            }
            __syncthreads();
            #pragma unroll
            for (int kk=0;kk<16;kk++){
                const float* ar = &As[kk*QG_AST + wn*64 + tn*8];
                ulonglong2 a01 = *(const ulonglong2*)ar;
                ulonglong2 a23 = *(const ulonglong2*)(ar+4);
                unsigned long long ra[4] = {a01.x, a01.y, a23.x, a23.y};
                const float* br = &Bq[kk*QG_BDUP + (wc*24 + tx*6)*2];
                ulonglong2 b01 = *(const ulonglong2*)br;
                ulonglong2 b23 = *(const ulonglong2*)(br+4);
                ulonglong2 b45 = *(const ulonglong2*)(br+8);
                unsigned long long bd[6] = {b01.x,b01.y,b23.x,b23.y,b45.x,b45.y};
                #pragma unroll
                for (int i=0;i<4;i++)
                    #pragma unroll
                    for (int j=0;j<6;j++)
                        fma2(acc[i][j], ra[i], bd[j]);
            }
            __syncthreads();
        }
    }
    #pragma unroll
    for (int i=0;i<4;i++){
        int nA = n0 + wn*64 + tn*8 + i*2;
        float z0 = 1.f / d_Z[h*N_NODES + nA];
        float z1 = 1.f / d_Z[h*N_NODES + nA + 1];
        #pragma unroll
        for (int j=0;j<6;j++){
            float2 v = unpk(acc[i][j]);
            int cm = cm0 + wc*24 + tx*6 + j;
            int c = cm / 9, m = cm - (cm/9)*9;
            d_accb[((size_t)nA*9     + m)*128 + h*16 + c] = v.x * z0;
            d_accb[((size_t)(nA+1)*9 + m)*128 + h*16 + c] = v.y * z1;
        }
    }
}

// ---------------- output GEMM: out[row,:] = accb[row,:] @ Wo ----------------
__global__ void __launch_bounds__(256) k_out(const float* __restrict__ Wo,
                                             float* __restrict__ out){
    __shared__ float Ash[32][128];
    int tid = threadIdx.x;
    int r0 = blockIdx.x * 32;
    for (int i=tid; i<32*128; i+=256)
        Ash[i/128][i%128] = d_accb[(size_t)(r0 + i/128)*128 + (i%128)];
    __syncthreads();
    float acc[32];
    #pragma unroll
    for (int r=0;r<32;r++) acc[r] = 0.f;
    for (int j=0;j<128;j++){
        float w = Wo[j*256 + tid];
        #pragma unroll
        for (int r=0;r<32;r++) acc[r] += Ash[r][j]*w;
    }
    #pragma unroll
    for (int r=0;r<32;r++)
        out[(size_t)(r0+r)*256 + tid] = acc[r];
}

// ---------------- launch -----------------------------------------------------
extern "C" void kernel_launch(void* const* d_in, const int* in_sizes, int n_in,
                              void* d_out, int out_size){
    const float* pos   = (const float*)d_in[0];
    const float* feat  = (const float*)d_in[1];
    const float* Wq    = (const float*)d_in[2];
    const float* Wk    = (const float*)d_in[3];
    const float* Wv    = (const float*)d_in[4];
    const float* Wo    = (const float*)d_in[5];
    const float* a     = (const float*)d_in[6];
    const float* kappa = (const float*)d_in[7];
    float* out = (float*)d_out;

    // order chosen so ncu's captured slot lands on k_keygemm
    k_sphere<<<1, 128>>>();                                           // 0
    k_features<<<N_NODES/NPB, 256>>>(pos, feat, Wq, Wk, Wv, kappa);   // 1
    k_cg<<<15, 128>>>();                                              // 2
    k_keygemm<<<dim3(X_DIM/128, 7), 128>>>();                         // 3
    k_rred<<<3, 256>>>();                                             // 4
    k_G<<<(K_DIM*U_DIM*H_DIM*81 + 255)/256, 256>>>(a);                // 5
    k_fold<<<(F_DIM*4096 + 255)/256, 256>>>();                        // 6
    k_ksum<<<256, 256>>>();                                           // 7
    k_Z<<<(N_NODES*H_DIM + 255)/256, 256>>>();                        // 8
    k_querygemm<<<dim3(3, N_NODES/128, H_DIM), 128>>>();              // 9
    k_out<<<(N_NODES*9)/32, 256>>>(Wo, out);                          // 10
}

// round 14
// speedup vs baseline: 1.0226x; 1.0226x over previous
#include <cuda_runtime.h>
#include <math.h>

#define N_NODES 2048
#define C_DIM   256
#define H_DIM   8
#define DQK_DIM 32
#define CV_DIM  16
#define K_DIM   8
#define U_DIM   25
#define F_DIM   400           // 2*K*U : cos block then sin block
#define X_DIM   36864         // H * DQK * CV * 9
#define XH_DIM  4608          // per-h slab of X

// ---------------- scratch (static __device__, no allocation) ----------------
__device__ float  d_qfT  [256 * N_NODES];
__device__ float  d_kfT  [256 * N_NODES];
__device__ float  d_vT   [1152 * N_NODES];
__device__ float  d_PhiT [F_DIM * N_NODES];
__device__ float  d_kfsum[256];
__device__ float  d_Z    [N_NODES * H_DIM];
__device__ float  d_Mbuf [(size_t)F_DIM * X_DIM];
__device__ float  d_Bbuf [(size_t)F_DIM * X_DIM];
__device__ float  d_accb [(size_t)N_NODES * 9 * 128];
__device__ float  d_G    [K_DIM * U_DIM * H_DIM * 81];
__device__ float  d_YW   [9 * U_DIM];
__device__ double d_Rs   [729];
__device__ float  d_RRED [729];
__device__ float  d_DIRS [U_DIM * 3];

__device__ __constant__ double c_fact[9] =
    {1.,1.,2.,6.,24.,120.,720.,5040.,40320.};

// ---------------- packed f32x2 helpers ---------------------------------------
__device__ __forceinline__ unsigned long long dup2(float a){
    unsigned long long r;
    asm("mov.b64 %0, {%1, %1};" : "=l"(r) : "f"(a));
    return r;
}
__device__ __forceinline__ void fma2(unsigned long long& d,
                                     unsigned long long a,
                                     unsigned long long b){
    asm("fma.rn.f32x2 %0, %1, %2, %0;" : "+l"(d) : "l"(a), "l"(b));
}
__device__ __forceinline__ float2 unpk(unsigned long long v){
    float2 r;
    asm("mov.b64 {%0, %1}, %2;" : "=f"(r.x), "=f"(r.y) : "l"(v));
    return r;
}

// ---------------- Clebsch-Gordan machinery (fp64, matches numpy) ------------
__device__ double cg_coef(int j1,int m1,int j2,int m2,int j,int m){
    if (m1 + m2 != m) return 0.0;
    int dj = j1 - j2; if (dj < 0) dj = -dj;
    if (j < dj || j > j1 + j2) return 0.0;
    double pref = sqrt((2.0*j+1.0) * c_fact[j+j1-j2] * c_fact[j-j1+j2] *
                       c_fact[j1+j2-j] / c_fact[j1+j2+j+1]);
    pref *= sqrt(c_fact[j+m]*c_fact[j-m]*c_fact[j1-m1]*c_fact[j1+m1]*
                 c_fact[j2-m2]*c_fact[j2+m2]);
    double s = 0.0;
    for (int k = 0; k <= j1 + j2 - j; k++){
        int d1=j1+j2-j-k, d2=j1-m1-k, d3=j2+m2-k, d4=j-j2+m1+k, d5=j-j1-m2+k;
        if (d1 < 0 || d2 < 0 || d3 < 0 || d4 < 0 || d5 < 0) continue;
        double term = 1.0/(c_fact[k]*c_fact[d1]*c_fact[d2]*c_fact[d3]*
                           c_fact[d4]*c_fact[d5]);
        s += (k & 1) ? -term : term;
    }
    return pref * s;
}

__device__ void umat_fill(int l, double* ur, double* ui){
    int n = 2*l + 1;
    for (int i = 0; i < n*n; i++){ ur[i] = 0.0; ui[i] = 0.0; }
    double s = 1.0 / sqrt(2.0);
    for (int m = -l; m <= l; m++){
        if (m > 0){
            ur[(l+m)*n + (l+m)] = (m & 1) ? -s : s;
            ur[(l+m)*n + (l-m)] = s;
        } else if (m == 0){
            ur[l*n + l] = 1.0;
        } else {
            int am = -m;
            ui[(l+m)*n + (l+m)] = s;
            ui[(l+m)*n + (l-m)] = (am & 1) ? s : -s;   // -(-1)^m * s
        }
    }
}

// ---------------- sphere grid + YW + zero d_Rs -------------------------------
__global__ void k_sphere(){
    const double PI = 3.14159265358979323846264338327950288;
    int tid = threadIdx.x;
    for (int i = tid; i < 729; i += blockDim.x) d_Rs[i] = 0.0;
    __shared__ double gx[5], gw[5];
    if (tid == 0){
        double x1 = sqrt(5.0 - 2.0*sqrt(10.0/7.0))/3.0;
        double x2 = sqrt(5.0 + 2.0*sqrt(10.0/7.0))/3.0;
        double w0 = 128.0/225.0;
        double w1 = (322.0 + 13.0*sqrt(70.0))/900.0;
        double w2 = (322.0 - 13.0*sqrt(70.0))/900.0;
        gx[0]=-x2; gx[1]=-x1; gx[2]=0.0; gx[3]=x1; gx[4]=x2;
        gw[0]=w2;  gw[1]=w1;  gw[2]=w0;  gw[3]=w1;  gw[4]=w2;
    }
    __syncthreads();
    if (tid < U_DIM){
        int ith = tid / 5, iph = tid % 5;
        double ct = gx[ith];
        double w  = gw[ith] * (2.0*PI/5.0);
        double ph = 2.0*PI*iph/5.0;
        double st = sqrt(fmax(1.0 - ct*ct, 0.0));
        double x = st*cos(ph), y = st*sin(ph), z = ct;
        d_DIRS[tid*3+0] = (float)x;
        d_DIRS[tid*3+1] = (float)y;
        d_DIRS[tid*3+2] = (float)z;
        double Y[9];
        Y[0]=0.282095; Y[1]=0.488603*y; Y[2]=0.488603*z; Y[3]=0.488603*x;
        Y[4]=1.092548*x*y; Y[5]=1.092548*y*z; Y[6]=0.315392*(3.0*z*z-1.0);
        Y[7]=1.092548*x*z; Y[8]=0.546274*(x*x-y*y);
        for (int e=0;e<9;e++) d_YW[e*U_DIM+tid] = (float)(Y[e]*w);
    }
}

// ---------------- CG: one (l1,l2,L) combo per block --------------------------
__global__ void k_cg(){
    __shared__ double cgc[125], rr[125], ri[125];
    __shared__ double U1r[25],U1i[25],U2r[25],U2i[25],U3r[25],U3i[25];
    __shared__ double nrm[2];
    const int l1s[15] = {0,0,0,1,1,1,1,1,1,2,2,2,2,2,2};
    const int l2s[15] = {0,1,2,0,1,1,1,2,2,0,1,1,2,2,2};
    const int Lss[15] = {0,1,2,1,0,1,2,1,2,2,1,2,0,1,2};
    const int off[3]  = {0,1,4};
    int b = blockIdx.x;
    int l1 = l1s[b], l2 = l2s[b], L = Lss[b];
    int tid = threadIdx.x;
    int n1 = 2*l1+1, n2 = 2*l2+1, n3 = 2*L+1;
    int tot = n1*n2*n3;
    for (int i=tid;i<tot;i+=blockDim.x){
        int i1=i/(n2*n3), i2=(i/n3)%n2, i3=i%n3;
        cgc[i] = cg_coef(l1, i1-l1, l2, i2-l2, L, i3-L);
    }
    if (tid==0){
        umat_fill(l1,U1r,U1i); umat_fill(l2,U2r,U2i); umat_fill(L,U3r,U3i);
        nrm[0]=0.0; nrm[1]=0.0;
    }
    __syncthreads();
    for (int i=tid;i<tot;i+=blockDim.x){
        int a=i/(n2*n3), bb=(i/n3)%n2, c=i%n3;
        double sr=0.0, si=0.0;
        for (int u=0;u<n1;u++)
        for (int v=0;v<n2;v++)
        for (int w=0;w<n3;w++){
            double cg = cgc[(u*n2+v)*n3+w];
            if (cg == 0.0) continue;
            double ar=U1r[a*n1+u], ai=U1i[a*n1+u];
            double br=U2r[bb*n2+v], bi=U2i[bb*n2+v];
            double cr=U3r[c*n3+w], ci=-U3i[c*n3+w];
            double pr=ar*br-ai*bi, pi=ar*bi+ai*br;
            sr += (pr*cr - pi*ci)*cg;
            si += (pr*ci + pi*cr)*cg;
        }
        rr[i]=sr; ri[i]=si;
        atomicAdd(&nrm[0], sr*sr);
        atomicAdd(&nrm[1], si*si);
    }
    __syncthreads();
    bool useRe = (nrm[0] >= nrm[1]);
    for (int i=tid;i<tot;i+=blockDim.x){
        int a=i/(n2*n3), bb=(i/n3)%n2, c=i%n3;
        double val = useRe ? rr[i] : ri[i];
        d_Rs[(off[l1]+a)*81 + (off[l2]+bb)*9 + (off[L]+c)] = val;
    }
}

// ---------------- RRED finalize ----------------------------------------------
__global__ void k_rred(){
    int i = blockIdx.x*blockDim.x + threadIdx.x;
    if (i >= 729) return;
    int m = i % 9;
    double cnt = (m==0) ? 3.0 : 6.0;
    d_RRED[i] = (float)(d_Rs[i]/cnt);
}

// ---------------- G[k,u,h,l,m] = sum_e YW[e,u]*a[ldeg(e),h,k]*RRED[e,l,m] ----
__global__ void k_G(const float* __restrict__ a){
    int idx = blockIdx.x*blockDim.x + threadIdx.x;
    if (idx >= K_DIM*U_DIM*H_DIM*81) return;
    int m = idx % 9, l = (idx/9)%9, h = (idx/81)%8, u = (idx/648)%25, k = idx/16200;
    const int ldeg[9] = {0,1,1,1,2,2,2,2,2};
    float s = 0.f;
    #pragma unroll
    for (int e=0;e<9;e++)
        s += d_YW[e*25+u] * a[ldeg[e]*64 + h*8 + k] * d_RRED[e*81 + l*9 + m];
    d_G[idx] = s;
}

// ---------------- per-node features (2 nodes / block) ------------------------
#define NPB 2
__global__ void k_features(const float* __restrict__ pos,
                           const float* __restrict__ feat,
                           const float* __restrict__ Wq,
                           const float* __restrict__ Wk,
                           const float* __restrict__ Wv,
                           const float* __restrict__ kappa){
    __shared__ float sf  [NPB][2304];
    __shared__ float s123[NPB][768];
    __shared__ float spos[NPB][3];
    __shared__ float skap[8];
    int tid = threadIdx.x;
    int n0  = blockIdx.x * NPB;
    if (tid < NPB*3) spos[tid/3][tid%3] = pos[n0*3 + tid];
    if (tid < 8) skap[tid] = kappa[tid];
    for (int nb=0; nb<NPB; nb++)
        for (int i=tid; i<2304; i+=256)
            sf[nb][i] = feat[(size_t)(n0+nb)*2304 + i];
    __syncthreads();
    for (int i=tid; i<NPB*256; i+=256){
        int nb = i/256, c = i%256;
        const float* f = sf[nb];
        s123[nb][c] = f[c];
        s123[nb][256+c] = sqrtf(f[256+c]*f[256+c] + f[512+c]*f[512+c] +
                                f[768+c]*f[768+c] + 1e-8f);
        float s = 1e-8f;
        #pragma unroll
        for (int m=4;m<9;m++){ float t = f[m*256+c]; s += t*t; }
        s123[nb][512+c] = sqrtf(s);
    }
    __syncthreads();

    // q,k projections: thread = output column j (0..255)
    {
        float qa[NPB] = {0,0}, ka[NPB] = {0,0};
        int j = tid;
        for (int g=0; g<3; g++){
            const float* wqb = Wq + g*65536 + j;
            const float* wkb = Wk + g*65536 + j;
            #pragma unroll 4
            for (int c=0;c<256;c++){
                float wq = wqb[c*256];
                float wk = wkb[c*256];
                #pragma unroll
                for (int nb=0;nb<NPB;nb++){
                    float s = s123[nb][g*256+c];
                    qa[nb] += s*wq; ka[nb] += s*wk;
                }
            }
        }
        #pragma unroll
        for (int nb=0;nb<NPB;nb++){
            int n = n0+nb;
            float q = qa[nb], k = ka[nb];
            float qf = (q > 0.f) ? q + 1.f : expf(q);
            float kf = (k > 0.f) ? k + 1.f : expf(k);
            d_qfT[(size_t)j*N_NODES + n] = qf;
            d_kfT[(size_t)j*N_NODES + n] = kf;
        }
    }

    // v: jv = h*16+c (0..127), one node per half-block
    {
        int jv = tid & 127, nb = tid >> 7;
        float acc[9];
        #pragma unroll
        for (int l=0;l<9;l++) acc[l] = 0.f;
        #pragma unroll 4
        for (int ch=0; ch<256; ch++){
            float w = Wv[ch*128 + jv];
            #pragma unroll
            for (int l=0;l<9;l++) acc[l] += sf[nb][l*256+ch]*w;
        }
        #pragma unroll
        for (int l=0;l<9;l++)
            d_vT[(size_t)(jv*9+l)*N_NODES + (n0+nb)] = acc[l];
    }

    // Phi
    for (int i=tid; i<NPB*200; i+=256){
        int nb = i/200, r = i%200;
        int k = r/25, u = r%25;
        float dot = spos[nb][0]*d_DIRS[u*3+0] + spos[nb][1]*d_DIRS[u*3+1] +
                    spos[nb][2]*d_DIRS[u*3+2];
        float ph = skap[k]*dot;
        float c, s;
        sincosf(ph, &s, &c);
        d_PhiT[(size_t)r      *N_NODES + n0+nb] = c;
        d_PhiT[(size_t)(200+r)*N_NODES + n0+nb] = s;
    }
}

// ---------------- kfsum + Z --------------------------------------------------
__global__ void k_ksum(){
    int j = blockIdx.x;
    int tid = threadIdx.x;
    float s = 0.f;
    for (int n=tid; n<N_NODES; n+=256) s += d_kfT[(size_t)j*N_NODES + n];
    #pragma unroll
    for (int o=16;o;o>>=1) s += __shfl_xor_sync(0xffffffffu, s, o);
    __shared__ float red[8];
    if ((tid & 31) == 0) red[tid>>5] = s;
    __syncthreads();
    if (tid == 0){
        float t = 0.f;
        #pragma unroll
        for (int w=0;w<8;w++) t += red[w];
        d_kfsum[j] = t;
    }
}

__global__ void k_Z(){
    int idx = blockIdx.x*blockDim.x + threadIdx.x;
    if (idx >= N_NODES*H_DIM) return;
    int n = idx % N_NODES, h = idx / N_NODES;
    float s = 0.f;
    #pragma unroll
    for (int d=0; d<32; d++)
        s += d_qfT[(size_t)(h*32+d)*N_NODES + n] * d_kfsum[h*32+d];
    d_Z[idx] = s + 1e-6f;
}

// ---------------- key GEMM: M[f,x] = sum_n Phi[f,n]*kf[hd(x),n]*v[hcl(x),n] --
// 4-CTA/SM variant: CTA 32f x 128x, 128 threads, K-chunk 16n,
// thread tile 4f x 8x (acc 32 regs), R6 fill/compute pattern
#define KG_AST 36     // 32 + 4 pad
#define KG_BST 132
__global__ void __launch_bounds__(128,4) k_keygemm(){
    __shared__ float As[16*KG_AST];
    __shared__ float Bs[16*KG_BST];
    int tid = threadIdx.x;
    int x0 = blockIdx.x * 128;
    int f0 = blockIdx.y * 32;
    int wid = tid>>5, lane = tid&31;
    int wf = wid>>1, wx = wid&1;      // warp grid 2f x 2x (16f x 64x per warp)
    int tf = lane&3, tx = lane>>2;    // thread grid 4f x 8x (4f x 8x per thread)
    int fr = tid&15, fcg = tid>>4;    // fill: n-row 0..15, col group 0..7

    unsigned kfo[16], vo[16];
    #pragma unroll
    for (int q=0;q<16;q++){
        int x = x0 + fcg + q*8;
        int h = x / XH_DIM, rem = x - h*XH_DIM;
        int d = rem / 144, cl = rem - d*144;
        kfo[q] = (unsigned)(h*32+d)*N_NODES;
        vo[q]  = (unsigned)(h*144+cl)*N_NODES;
    }
    unsigned long long acc[4][4];
    #pragma unroll
    for (int i=0;i<4;i++)
        #pragma unroll
        for (int j=0;j<4;j++) acc[i][j] = 0ull;

    for (int nb=0; nb<N_NODES; nb+=16){
        #pragma unroll
        for (int q=0;q<4;q++){
            int col = fcg + q*8;
            int f = f0 + col;
            As[fr*KG_AST + col] = (f < F_DIM) ? d_PhiT[(size_t)f*N_NODES + nb + fr] : 0.f;
        }
        #pragma unroll
        for (int q=0;q<16;q++){
            int col = fcg + q*8;
            Bs[fr*KG_BST + col] = d_kfT[kfo[q] + nb + fr] * d_vT[vo[q] + nb + fr];
        }
        __syncthreads();
        #pragma unroll
        for (int kk=0;kk<16;kk++){
            const float* ar = &As[kk*KG_AST + wf*16 + tf*4];
            float4 a0 = *(const float4*)ar;
            unsigned long long ad[4];
            ad[0]=dup2(a0.x); ad[1]=dup2(a0.y); ad[2]=dup2(a0.z); ad[3]=dup2(a0.w);
            const float* br = &Bs[kk*KG_BST + wx*64 + tx*8];
            ulonglong2 b01 = *(const ulonglong2*)br;
            ulonglong2 b23 = *(const ulonglong2*)(br+4);
            #pragma unroll
            for (int i=0;i<4;i++){
                fma2(acc[i][0], ad[i], b01.x);
                fma2(acc[i][1], ad[i], b01.y);
                fma2(acc[i][2], ad[i], b23.x);
                fma2(acc[i][3], ad[i], b23.y);
            }
        }
        __syncthreads();
    }
    #pragma unroll
    for (int i=0;i<4;i++){
        int f = f0 + wf*16 + tf*4 + i;
        if (f >= F_DIM) continue;
        float* mrow = d_Mbuf + (size_t)f*X_DIM + x0 + wx*64 + tx*8;
        ulonglong2 s0; s0.x = acc[i][0]; s0.y = acc[i][1];
        ulonglong2 s1; s1.x = acc[i][2]; s1.y = acc[i][3];
        *(ulonglong2*)&mrow[0] = s0;
        *(ulonglong2*)&mrow[4] = s1;
    }
}

// ---------------- fold: B[f,h,d,c,m] = sum_l M[f,h,d,c,l]*G[k,u,h,l,m] -------
__global__ void k_fold(){
    int idx = blockIdx.x*blockDim.x + threadIdx.x;
    if (idx >= F_DIM*4096) return;
    int c = idx % 16, d = (idx/16)%32, h = (idx/512)%8, f = idx/4096;
    int k = (f % 200) / 25, u = f % 25;
    const float* g = d_G + (size_t)((k*25+u)*8 + h)*81;
    size_t base = (size_t)f*X_DIM + h*XH_DIM + d*144 + c*9;
    float mrow[9];
    #pragma unroll
    for (int l=0;l<9;l++) mrow[l] = d_Mbuf[base+l];
    #pragma unroll
    for (int m=0;m<9;m++){
        float s = 0.f;
        #pragma unroll
        for (int l=0;l<9;l++) s += mrow[l]*g[l*9+m];
        d_Bbuf[base+m] = s;
    }
}

// ---------------- query GEMM: acc[n,cm] = sum_{f,d} Phi*qf*B ------------------
// R6 champion kernel, unchanged
#define QG_AST 132
#define QG_BST 50
__global__ void __launch_bounds__(128,3) k_querygemm(){
    __shared__ float As[16*QG_AST];
    __shared__ float Bs[16*QG_BST];
    int tid = threadIdx.x;
    int cm0 = blockIdx.x * 48;
    int n0  = blockIdx.y * 128;
    int h   = blockIdx.z;
    int wid = tid>>5, lane = tid&31;
    int wn = wid>>1, wc = wid&1;      // warp grid 2n x 2cm
    int tn = lane>>2, tx = lane&3;    // thread grid 8n x 4cm

    float qreg[32];
    #pragma unroll
    for (int d=0;d<32;d++)
        qreg[d] = d_qfT[(size_t)(h*32+d)*N_NODES + n0 + tid];

    unsigned long long acc[4][6];
    #pragma unroll
    for (int i=0;i<4;i++)
        #pragma unroll
        for (int j=0;j<6;j++) acc[i][j] = 0ull;

    for (int f=0; f<F_DIM; f++){
        float ph = d_PhiT[(size_t)f*N_NODES + n0 + tid];
        const float* bb = d_Bbuf + (size_t)f*X_DIM + h*XH_DIM + cm0;
        #pragma unroll
        for (int hb=0; hb<2; hb++){
            #pragma unroll
            for (int dl=0; dl<16; dl++)
                As[dl*QG_AST + tid] = ph * qreg[hb*16 + dl];
            #pragma unroll
            for (int j=0;j<6;j++){
                int idx = tid + j*128;
                int r = idx/48, c = idx - r*48;
                Bs[r*QG_BST + c] = bb[(hb*16 + r)*144 + c];
            }
            __syncthreads();
            #pragma unroll
            for (int kk=0;kk<16;kk++){
                const float* ar = &As[kk*QG_AST + wn*64 + tn*8];
                ulonglong2 a01 = *(const ulonglong2*)ar;
                ulonglong2 a23 = *(const ulonglong2*)(ar+4);
                unsigned long long ra[4] = {a01.x, a01.y, a23.x, a23.y};
                const float* br = &Bs[kk*QG_BST + wc*24 + tx*6];
                float2 p0 = *(const float2*)br;
                float2 p1 = *(const float2*)(br+2);
                float2 p2 = *(const float2*)(br+4);
                unsigned long long bd[6];
                bd[0]=dup2(p0.x); bd[1]=dup2(p0.y); bd[2]=dup2(p1.x);
                bd[3]=dup2(p1.y); bd[4]=dup2(p2.x); bd[5]=dup2(p2.y);
                #pragma unroll
                for (int i=0;i<4;i++)
                    #pragma unroll
                    for (int j=0;j<6;j++)
                        fma2(acc[i][j], ra[i], bd[j]);
            }
            __syncthreads();
        }
    }
    #pragma unroll
    for (int i=0;i<4;i++){
        int nA = n0 + wn*64 + tn*8 + i*2;
        float z0 = 1.f / d_Z[h*N_NODES + nA];
        float z1 = 1.f / d_Z[h*N_NODES + nA + 1];
        #pragma unroll
        for (int j=0;j<6;j++){
            float2 v = unpk(acc[i][j]);
            int cm = cm0 + wc*24 + tx*6 + j;
            int c = cm / 9, m = cm - (cm/9)*9;
            d_accb[((size_t)nA*9     + m)*128 + h*16 + c] = v.x * z0;
            d_accb[((size_t)(nA+1)*9 + m)*128 + h*16 + c] = v.y * z1;
        }
    }
}

// ---------------- output GEMM: out[row,:] = accb[row,:] @ Wo ----------------
__global__ void __launch_bounds__(256) k_out(const float* __restrict__ Wo,
                                             float* __restrict__ out){
    __shared__ float Ash[32][128];
    int tid = threadIdx.x;
    int r0 = blockIdx.x * 32;
    for (int i=tid; i<32*128; i+=256)
        Ash[i/128][i%128] = d_accb[(size_t)(r0 + i/128)*128 + (i%128)];
    __syncthreads();
    float acc[32];
    #pragma unroll
    for (int r=0;r<32;r++) acc[r] = 0.f;
    for (int j=0;j<128;j++){
        float w = Wo[j*256 + tid];
        #pragma unroll
        for (int r=0;r<32;r++) acc[r] += Ash[r][j]*w;
    }
    #pragma unroll
    for (int r=0;r<32;r++)
        out[(size_t)(r0+r)*256 + tid] = acc[r];
}

// ---------------- launch -----------------------------------------------------
extern "C" void kernel_launch(void* const* d_in, const int* in_sizes, int n_in,
                              void* d_out, int out_size){
    const float* pos   = (const float*)d_in[0];
    const float* feat  = (const float*)d_in[1];
    const float* Wq    = (const float*)d_in[2];
    const float* Wk    = (const float*)d_in[3];
    const float* Wv    = (const float*)d_in[4];
    const float* Wo    = (const float*)d_in[5];
    const float* a     = (const float*)d_in[6];
    const float* kappa = (const float*)d_in[7];
    float* out = (float*)d_out;

    // order chosen so ncu's captured slot lands on k_keygemm
    k_sphere<<<1, 128>>>();                                           // 0
    k_features<<<N_NODES/NPB, 256>>>(pos, feat, Wq, Wk, Wv, kappa);   // 1
    k_cg<<<15, 128>>>();                                              // 2
    k_keygemm<<<dim3(X_DIM/128, 13), 128>>>();                        // 3
    k_rred<<<3, 256>>>();                                             // 4
    k_G<<<(K_DIM*U_DIM*H_DIM*81 + 255)/256, 256>>>(a);                // 5
    k_fold<<<(F_DIM*4096 + 255)/256, 256>>>();                        // 6
    k_ksum<<<256, 256>>>();                                           // 7
    k_Z<<<(N_NODES*H_DIM + 255)/256, 256>>>();                        // 8
    k_querygemm<<<dim3(3, N_NODES/128, H_DIM), 128>>>();              // 9
    k_out<<<(N_NODES*9)/32, 256>>>(Wo, out);                          // 10
}

// round 15
// speedup vs baseline: 1.1025x; 1.0781x over previous
#include <cuda_runtime.h>
#include <math.h>

#define N_NODES 2048
#define C_DIM   256
#define H_DIM   8
#define DQK_DIM 32
#define CV_DIM  16
#define K_DIM   8
#define U_DIM   25
#define F_DIM   400           // 2*K*U : cos block then sin block
#define X_DIM   36864         // H * DQK * CV * 9
#define XH_DIM  4608          // per-h slab of X

// ---------------- scratch (static __device__, no allocation) ----------------
__device__ float  d_qfT  [256 * N_NODES];
__device__ float  d_kfT  [256 * N_NODES];
__device__ float  d_vT   [1152 * N_NODES];
__device__ float  d_PhiT [F_DIM * N_NODES];
__device__ float  d_kfsum[256];
__device__ float  d_Z    [N_NODES * H_DIM];
__device__ float  d_Mbuf [(size_t)F_DIM * X_DIM];
__device__ float  d_Bbuf [(size_t)F_DIM * X_DIM];
__device__ float  d_accb [(size_t)N_NODES * 9 * 128];
__device__ float  d_G    [K_DIM * U_DIM * H_DIM * 81];
__device__ float  d_YW   [9 * U_DIM];
__device__ double d_Rs   [729];
__device__ float  d_RRED [729];
__device__ float  d_DIRS [U_DIM * 3];

__device__ __constant__ double c_fact[9] =
    {1.,1.,2.,6.,24.,120.,720.,5040.,40320.};

// ---------------- packed f32x2 helpers ---------------------------------------
__device__ __forceinline__ unsigned long long dup2(float a){
    unsigned long long r;
    asm("mov.b64 %0, {%1, %1};" : "=l"(r) : "f"(a));
    return r;
}
__device__ __forceinline__ void fma2(unsigned long long& d,
                                     unsigned long long a,
                                     unsigned long long b){
    asm("fma.rn.f32x2 %0, %1, %2, %0;" : "+l"(d) : "l"(a), "l"(b));
}
__device__ __forceinline__ float2 unpk(unsigned long long v){
    float2 r;
    asm("mov.b64 {%0, %1}, %2;" : "=f"(r.x), "=f"(r.y) : "l"(v));
    return r;
}

// ---------------- Clebsch-Gordan machinery (fp64, matches numpy) ------------
__device__ double cg_coef(int j1,int m1,int j2,int m2,int j,int m){
    if (m1 + m2 != m) return 0.0;
    int dj = j1 - j2; if (dj < 0) dj = -dj;
    if (j < dj || j > j1 + j2) return 0.0;
    double pref = sqrt((2.0*j+1.0) * c_fact[j+j1-j2] * c_fact[j-j1+j2] *
                       c_fact[j1+j2-j] / c_fact[j1+j2+j+1]);
    pref *= sqrt(c_fact[j+m]*c_fact[j-m]*c_fact[j1-m1]*c_fact[j1+m1]*
                 c_fact[j2-m2]*c_fact[j2+m2]);
    double s = 0.0;
    for (int k = 0; k <= j1 + j2 - j; k++){
        int d1=j1+j2-j-k, d2=j1-m1-k, d3=j2+m2-k, d4=j-j2+m1+k, d5=j-j1-m2+k;
        if (d1 < 0 || d2 < 0 || d3 < 0 || d4 < 0 || d5 < 0) continue;
        double term = 1.0/(c_fact[k]*c_fact[d1]*c_fact[d2]*c_fact[d3]*
                           c_fact[d4]*c_fact[d5]);
        s += (k & 1) ? -term : term;
    }
    return pref * s;
}

__device__ void umat_fill(int l, double* ur, double* ui){
    int n = 2*l + 1;
    for (int i = 0; i < n*n; i++){ ur[i] = 0.0; ui[i] = 0.0; }
    double s = 1.0 / sqrt(2.0);
    for (int m = -l; m <= l; m++){
        if (m > 0){
            ur[(l+m)*n + (l+m)] = (m & 1) ? -s : s;
            ur[(l+m)*n + (l-m)] = s;
        } else if (m == 0){
            ur[l*n + l] = 1.0;
        } else {
            int am = -m;
            ui[(l+m)*n + (l+m)] = s;
            ui[(l+m)*n + (l-m)] = (am & 1) ? s : -s;   // -(-1)^m * s
        }
    }
}

// ---------------- sphere grid + YW + zero d_Rs -------------------------------
__global__ void k_sphere(){
    const double PI = 3.14159265358979323846264338327950288;
    int tid = threadIdx.x;
    for (int i = tid; i < 729; i += blockDim.x) d_Rs[i] = 0.0;
    __shared__ double gx[5], gw[5];
    if (tid == 0){
        double x1 = sqrt(5.0 - 2.0*sqrt(10.0/7.0))/3.0;
        double x2 = sqrt(5.0 + 2.0*sqrt(10.0/7.0))/3.0;
        double w0 = 128.0/225.0;
        double w1 = (322.0 + 13.0*sqrt(70.0))/900.0;
        double w2 = (322.0 - 13.0*sqrt(70.0))/900.0;
        gx[0]=-x2; gx[1]=-x1; gx[2]=0.0; gx[3]=x1; gx[4]=x2;
        gw[0]=w2;  gw[1]=w1;  gw[2]=w0;  gw[3]=w1;  gw[4]=w2;
    }
    __syncthreads();
    if (tid < U_DIM){
        int ith = tid / 5, iph = tid % 5;
        double ct = gx[ith];
        double w  = gw[ith] * (2.0*PI/5.0);
        double ph = 2.0*PI*iph/5.0;
        double st = sqrt(fmax(1.0 - ct*ct, 0.0));
        double x = st*cos(ph), y = st*sin(ph), z = ct;
        d_DIRS[tid*3+0] = (float)x;
        d_DIRS[tid*3+1] = (float)y;
        d_DIRS[tid*3+2] = (float)z;
        double Y[9];
        Y[0]=0.282095; Y[1]=0.488603*y; Y[2]=0.488603*z; Y[3]=0.488603*x;
        Y[4]=1.092548*x*y; Y[5]=1.092548*y*z; Y[6]=0.315392*(3.0*z*z-1.0);
        Y[7]=1.092548*x*z; Y[8]=0.546274*(x*x-y*y);
        for (int e=0;e<9;e++) d_YW[e*U_DIM+tid] = (float)(Y[e]*w);
    }
}

// ---------------- CG: one (l1,l2,L) combo per block --------------------------
__global__ void k_cg(){
    __shared__ double cgc[125], rr[125], ri[125];
    __shared__ double U1r[25],U1i[25],U2r[25],U2i[25],U3r[25],U3i[25];
    __shared__ double nrm[2];
    const int l1s[15] = {0,0,0,1,1,1,1,1,1,2,2,2,2,2,2};
    const int l2s[15] = {0,1,2,0,1,1,1,2,2,0,1,1,2,2,2};
    const int Lss[15] = {0,1,2,1,0,1,2,1,2,2,1,2,0,1,2};
    const int off[3]  = {0,1,4};
    int b = blockIdx.x;
    int l1 = l1s[b], l2 = l2s[b], L = Lss[b];
    int tid = threadIdx.x;
    int n1 = 2*l1+1, n2 = 2*l2+1, n3 = 2*L+1;
    int tot = n1*n2*n3;
    for (int i=tid;i<tot;i+=blockDim.x){
        int i1=i/(n2*n3), i2=(i/n3)%n2, i3=i%n3;
        cgc[i] = cg_coef(l1, i1-l1, l2, i2-l2, L, i3-L);
    }
    if (tid==0){
        umat_fill(l1,U1r,U1i); umat_fill(l2,U2r,U2i); umat_fill(L,U3r,U3i);
        nrm[0]=0.0; nrm[1]=0.0;
    }
    __syncthreads();
    for (int i=tid;i<tot;i+=blockDim.x){
        int a=i/(n2*n3), bb=(i/n3)%n2, c=i%n3;
        double sr=0.0, si=0.0;
        for (int u=0;u<n1;u++)
        for (int v=0;v<n2;v++)
        for (int w=0;w<n3;w++){
            double cg = cgc[(u*n2+v)*n3+w];
            if (cg == 0.0) continue;
            double ar=U1r[a*n1+u], ai=U1i[a*n1+u];
            double br=U2r[bb*n2+v], bi=U2i[bb*n2+v];
            double cr=U3r[c*n3+w], ci=-U3i[c*n3+w];
            double pr=ar*br-ai*bi, pi=ar*bi+ai*br;
            sr += (pr*cr - pi*ci)*cg;
            si += (pr*ci + pi*cr)*cg;
        }
        rr[i]=sr; ri[i]=si;
        atomicAdd(&nrm[0], sr*sr);
        atomicAdd(&nrm[1], si*si);
    }
    __syncthreads();
    bool useRe = (nrm[0] >= nrm[1]);
    for (int i=tid;i<tot;i+=blockDim.x){
        int a=i/(n2*n3), bb=(i/n3)%n2, c=i%n3;
        double val = useRe ? rr[i] : ri[i];
        d_Rs[(off[l1]+a)*81 + (off[l2]+bb)*9 + (off[L]+c)] = val;
    }
}

// ---------------- RRED finalize ----------------------------------------------
__global__ void k_rred(){
    int i = blockIdx.x*blockDim.x + threadIdx.x;
    if (i >= 729) return;
    int m = i % 9;
    double cnt = (m==0) ? 3.0 : 6.0;
    d_RRED[i] = (float)(d_Rs[i]/cnt);
}

// ---------------- G[k,u,h,l,m] = sum_e YW[e,u]*a[ldeg(e),h,k]*RRED[e,l,m] ----
__global__ void k_G(const float* __restrict__ a){
    int idx = blockIdx.x*blockDim.x + threadIdx.x;
    if (idx >= K_DIM*U_DIM*H_DIM*81) return;
    int m = idx % 9, l = (idx/9)%9, h = (idx/81)%8, u = (idx/648)%25, k = idx/16200;
    const int ldeg[9] = {0,1,1,1,2,2,2,2,2};
    float s = 0.f;
    #pragma unroll
    for (int e=0;e<9;e++)
        s += d_YW[e*25+u] * a[ldeg[e]*64 + h*8 + k] * d_RRED[e*81 + l*9 + m];
    d_G[idx] = s;
}

// ---------------- per-node features (2 nodes / block) ------------------------
#define NPB 2
__global__ void k_features(const float* __restrict__ pos,
                           const float* __restrict__ feat,
                           const float* __restrict__ Wq,
                           const float* __restrict__ Wk,
                           const float* __restrict__ Wv,
                           const float* __restrict__ kappa){
    __shared__ float sf  [NPB][2304];
    __shared__ float s123[NPB][768];
    __shared__ float spos[NPB][3];
    __shared__ float skap[8];
    int tid = threadIdx.x;
    int n0  = blockIdx.x * NPB;
    if (tid < NPB*3) spos[tid/3][tid%3] = pos[n0*3 + tid];
    if (tid < 8) skap[tid] = kappa[tid];
    for (int nb=0; nb<NPB; nb++)
        for (int i=tid; i<2304; i+=256)
            sf[nb][i] = feat[(size_t)(n0+nb)*2304 + i];
    __syncthreads();
    for (int i=tid; i<NPB*256; i+=256){
        int nb = i/256, c = i%256;
        const float* f = sf[nb];
        s123[nb][c] = f[c];
        s123[nb][256+c] = sqrtf(f[256+c]*f[256+c] + f[512+c]*f[512+c] +
                                f[768+c]*f[768+c] + 1e-8f);
        float s = 1e-8f;
        #pragma unroll
        for (int m=4;m<9;m++){ float t = f[m*256+c]; s += t*t; }
        s123[nb][512+c] = sqrtf(s);
    }
    __syncthreads();

    // q,k projections: thread = output column j (0..255)
    {
        float qa[NPB] = {0,0}, ka[NPB] = {0,0};
        int j = tid;
        for (int g=0; g<3; g++){
            const float* wqb = Wq + g*65536 + j;
            const float* wkb = Wk + g*65536 + j;
            #pragma unroll 4
            for (int c=0;c<256;c++){
                float wq = wqb[c*256];
                float wk = wkb[c*256];
                #pragma unroll
                for (int nb=0;nb<NPB;nb++){
                    float s = s123[nb][g*256+c];
                    qa[nb] += s*wq; ka[nb] += s*wk;
                }
            }
        }
        #pragma unroll
        for (int nb=0;nb<NPB;nb++){
            int n = n0+nb;
            float q = qa[nb], k = ka[nb];
            float qf = (q > 0.f) ? q + 1.f : expf(q);
            float kf = (k > 0.f) ? k + 1.f : expf(k);
            d_qfT[(size_t)j*N_NODES + n] = qf;
            d_kfT[(size_t)j*N_NODES + n] = kf;
        }
    }

    // v: jv = h*16+c (0..127), one node per half-block
    {
        int jv = tid & 127, nb = tid >> 7;
        float acc[9];
        #pragma unroll
        for (int l=0;l<9;l++) acc[l] = 0.f;
        #pragma unroll 4
        for (int ch=0; ch<256; ch++){
            float w = Wv[ch*128 + jv];
            #pragma unroll
            for (int l=0;l<9;l++) acc[l] += sf[nb][l*256+ch]*w;
        }
        #pragma unroll
        for (int l=0;l<9;l++)
            d_vT[(size_t)(jv*9+l)*N_NODES + (n0+nb)] = acc[l];
    }

    // Phi
    for (int i=tid; i<NPB*200; i+=256){
        int nb = i/200, r = i%200;
        int k = r/25, u = r%25;
        float dot = spos[nb][0]*d_DIRS[u*3+0] + spos[nb][1]*d_DIRS[u*3+1] +
                    spos[nb][2]*d_DIRS[u*3+2];
        float ph = skap[k]*dot;
        float c, s;
        sincosf(ph, &s, &c);
        d_PhiT[(size_t)r      *N_NODES + n0+nb] = c;
        d_PhiT[(size_t)(200+r)*N_NODES + n0+nb] = s;
    }
}

// ---------------- kfsum + Z --------------------------------------------------
__global__ void k_ksum(){
    int j = blockIdx.x;
    int tid = threadIdx.x;
    float s = 0.f;
    for (int n=tid; n<N_NODES; n+=256) s += d_kfT[(size_t)j*N_NODES + n];
    #pragma unroll
    for (int o=16;o;o>>=1) s += __shfl_xor_sync(0xffffffffu, s, o);
    __shared__ float red[8];
    if ((tid & 31) == 0) red[tid>>5] = s;
    __syncthreads();
    if (tid == 0){
        float t = 0.f;
        #pragma unroll
        for (int w=0;w<8;w++) t += red[w];
        d_kfsum[j] = t;
    }
}

__global__ void k_Z(){
    int idx = blockIdx.x*blockDim.x + threadIdx.x;
    if (idx >= N_NODES*H_DIM) return;
    int n = idx % N_NODES, h = idx / N_NODES;
    float s = 0.f;
    #pragma unroll
    for (int d=0; d<32; d++)
        s += d_qfT[(size_t)(h*32+d)*N_NODES + n] * d_kfsum[h*32+d];
    d_Z[idx] = s + 1e-6f;
}

// ---------------- key GEMM: M[f,x] = sum_n Phi[f,n]*kf[hd(x),n]*v[hcl(x),n] --
// R6 tile/inner body; K-chunk deepened to 32 (fills amortized 2x, barriers halved)
#define KG_AST 68
#define KG_BST 132
__global__ void __launch_bounds__(128,3) k_keygemm(){
    __shared__ float As[32*KG_AST];
    __shared__ float Bs[32*KG_BST];
    int tid = threadIdx.x;
    int x0 = blockIdx.x * 128;
    int f0 = blockIdx.y * 64;
    int wid = tid>>5, lane = tid&31;
    int wf = wid>>1, wx = wid&1;      // warp grid 2f x 2x
    int tf = lane&3, tx = lane>>2;    // thread grid 4f x 8x
    int fr = tid&15, fcg = tid>>4;    // fill: n-row 0..15 (+16), col group 0..7

    unsigned kfo[16], vo[16];
    #pragma unroll
    for (int q=0;q<16;q++){
        int x = x0 + fcg + q*8;
        int h = x / XH_DIM, rem = x - h*XH_DIM;
        int d = rem / 144, cl = rem - d*144;
        kfo[q] = (unsigned)(h*32+d)*N_NODES;
        vo[q]  = (unsigned)(h*144+cl)*N_NODES;
    }
    unsigned long long acc[8][4];
    #pragma unroll
    for (int i=0;i<8;i++)
        #pragma unroll
        for (int j=0;j<4;j++) acc[i][j] = 0ull;

    for (int nb=0; nb<N_NODES; nb+=32){
        #pragma unroll
        for (int rh=0; rh<2; rh++){
            int row = fr + rh*16;
            #pragma unroll
            for (int q=0;q<8;q++){
                int col = fcg + q*8;
                int f = f0 + col;
                As[row*KG_AST + col] = (f < F_DIM) ?
                    d_PhiT[(size_t)f*N_NODES + nb + row] : 0.f;
            }
            #pragma unroll
            for (int q=0;q<16;q++){
                int col = fcg + q*8;
                Bs[row*KG_BST + col] =
                    d_kfT[kfo[q] + nb + row] * d_vT[vo[q] + nb + row];
            }
        }
        __syncthreads();
        #pragma unroll
        for (int kk=0;kk<32;kk++){
            const float* ar = &As[kk*KG_AST + wf*32 + tf*8];
            float4 a0 = *(const float4*)ar;
            float4 a1 = *(const float4*)(ar+4);
            unsigned long long ad[8];
            ad[0]=dup2(a0.x); ad[1]=dup2(a0.y); ad[2]=dup2(a0.z); ad[3]=dup2(a0.w);
            ad[4]=dup2(a1.x); ad[5]=dup2(a1.y); ad[6]=dup2(a1.z); ad[7]=dup2(a1.w);
            const float* br = &Bs[kk*KG_BST + wx*64 + tx*8];
            ulonglong2 b01 = *(const ulonglong2*)br;
            ulonglong2 b23 = *(const ulonglong2*)(br+4);
            #pragma unroll
            for (int i=0;i<8;i++){
                fma2(acc[i][0], ad[i], b01.x);
                fma2(acc[i][1], ad[i], b01.y);
                fma2(acc[i][2], ad[i], b23.x);
                fma2(acc[i][3], ad[i], b23.y);
            }
        }
        __syncthreads();
    }
    #pragma unroll
    for (int i=0;i<8;i++){
        int f = f0 + wf*32 + tf*8 + i;
        if (f >= F_DIM) continue;
        float* mrow = d_Mbuf + (size_t)f*X_DIM + x0 + wx*64 + tx*8;
        ulonglong2 s0; s0.x = acc[i][0]; s0.y = acc[i][1];
        ulonglong2 s1; s1.x = acc[i][2]; s1.y = acc[i][3];
        *(ulonglong2*)&mrow[0] = s0;
        *(ulonglong2*)&mrow[4] = s1;
    }
}

// ---------------- fold: B[f,h,d,c,m] = sum_l M[f,h,d,c,l]*G[k,u,h,l,m] -------
__global__ void k_fold(){
    int idx = blockIdx.x*blockDim.x + threadIdx.x;
    if (idx >= F_DIM*4096) return;
    int c = idx % 16, d = (idx/16)%32, h = (idx/512)%8, f = idx/4096;
    int k = (f % 200) / 25, u = f % 25;
    const float* g = d_G + (size_t)((k*25+u)*8 + h)*81;
    size_t base = (size_t)f*X_DIM + h*XH_DIM + d*144 + c*9;
    float mrow[9];
    #pragma unroll
    for (int l=0;l<9;l++) mrow[l] = d_Mbuf[base+l];
    #pragma unroll
    for (int m=0;m<9;m++){
        float s = 0.f;
        #pragma unroll
        for (int l=0;l<9;l++) s += mrow[l]*g[l*9+m];
        d_Bbuf[base+m] = s;
    }
}

// ---------------- query GEMM: acc[n,cm] = sum_{f,d} Phi*qf*B ------------------
// R6 inner body; hb half-chunks merged to one K=32 chunk (barriers halved)
#define QG_AST 132
#define QG_BST 50
__global__ void __launch_bounds__(128,3) k_querygemm(){
    __shared__ float As[32*QG_AST];
    __shared__ float Bs[32*QG_BST];
    int tid = threadIdx.x;
    int cm0 = blockIdx.x * 48;
    int n0  = blockIdx.y * 128;
    int h   = blockIdx.z;
    int wid = tid>>5, lane = tid&31;
    int wn = wid>>1, wc = wid&1;      // warp grid 2n x 2cm
    int tn = lane>>2, tx = lane&3;    // thread grid 8n x 4cm

    float qreg[32];
    #pragma unroll
    for (int d=0;d<32;d++)
        qreg[d] = d_qfT[(size_t)(h*32+d)*N_NODES + n0 + tid];

    unsigned long long acc[4][6];
    #pragma unroll
    for (int i=0;i<4;i++)
        #pragma unroll
        for (int j=0;j<6;j++) acc[i][j] = 0ull;

    for (int f=0; f<F_DIM; f++){
        float ph = d_PhiT[(size_t)f*N_NODES + n0 + tid];
        const float* bb = d_Bbuf + (size_t)f*X_DIM + h*XH_DIM + cm0;
        #pragma unroll
        for (int dl=0; dl<32; dl++)
            As[dl*QG_AST + tid] = ph * qreg[dl];
        #pragma unroll
        for (int j=0;j<12;j++){
            int idx = tid + j*128;
            int r = idx/48, c = idx - r*48;
            Bs[r*QG_BST + c] = bb[r*144 + c];
        }
        __syncthreads();
        #pragma unroll
        for (int kk=0;kk<32;kk++){
            const float* ar = &As[kk*QG_AST + wn*64 + tn*8];
            ulonglong2 a01 = *(const ulonglong2*)ar;
            ulonglong2 a23 = *(const ulonglong2*)(ar+4);
            unsigned long long ra[4] = {a01.x, a01.y, a23.x, a23.y};
            const float* br = &Bs[kk*QG_BST + wc*24 + tx*6];
            float2 p0 = *(const float2*)br;
            float2 p1 = *(const float2*)(br+2);
            float2 p2 = *(const float2*)(br+4);
            unsigned long long bd[6];
            bd[0]=dup2(p0.x); bd[1]=dup2(p0.y); bd[2]=dup2(p1.x);
            bd[3]=dup2(p1.y); bd[4]=dup2(p2.x); bd[5]=dup2(p2.y);
            #pragma unroll
            for (int i=0;i<4;i++)
                #pragma unroll
                for (int j=0;j<6;j++)
                    fma2(acc[i][j], ra[i], bd[j]);
        }
        __syncthreads();
    }
    #pragma unroll
    for (int i=0;i<4;i++){
        int nA = n0 + wn*64 + tn*8 + i*2;
        float z0 = 1.f / d_Z[h*N_NODES + nA];
        float z1 = 1.f / d_Z[h*N_NODES + nA + 1];
        #pragma unroll
        for (int j=0;j<6;j++){
            float2 v = unpk(acc[i][j]);
            int cm = cm0 + wc*24 + tx*6 + j;
            int c = cm / 9, m = cm - (cm/9)*9;
            d_accb[((size_t)nA*9     + m)*128 + h*16 + c] = v.x * z0;
            d_accb[((size_t)(nA+1)*9 + m)*128 + h*16 + c] = v.y * z1;
        }
    }
}

// ---------------- output GEMM: out[row,:] = accb[row,:] @ Wo ----------------
__global__ void __launch_bounds__(256) k_out(const float* __restrict__ Wo,
                                             float* __restrict__ out){
    __shared__ float Ash[32][128];
    int tid = threadIdx.x;
    int r0 = blockIdx.x * 32;
    for (int i=tid; i<32*128; i+=256)
        Ash[i/128][i%128] = d_accb[(size_t)(r0 + i/128)*128 + (i%128)];
    __syncthreads();
    float acc[32];
    #pragma unroll
    for (int r=0;r<32;r++) acc[r] = 0.f;
    for (int j=0;j<128;j++){
        float w = Wo[j*256 + tid];
        #pragma unroll
        for (int r=0;r<32;r++) acc[r] += Ash[r][j]*w;
    }
    #pragma unroll
    for (int r=0;r<32;r++)
        out[(size_t)(r0+r)*256 + tid] = acc[r];
}

// ---------------- launch -----------------------------------------------------
extern "C" void kernel_launch(void* const* d_in, const int* in_sizes, int n_in,
                              void* d_out, int out_size){
    const float* pos   = (const float*)d_in[0];
    const float* feat  = (const float*)d_in[1];
    const float* Wq    = (const float*)d_in[2];
    const float* Wk    = (const float*)d_in[3];
    const float* Wv    = (const float*)d_in[4];
    const float* Wo    = (const float*)d_in[5];
    const float* a     = (const float*)d_in[6];
    const float* kappa = (const float*)d_in[7];
    float* out = (float*)d_out;

    // order chosen so ncu's captured slot lands on k_keygemm
    k_sphere<<<1, 128>>>();                                           // 0
    k_features<<<N_NODES/NPB, 256>>>(pos, feat, Wq, Wk, Wv, kappa);   // 1
    k_cg<<<15, 128>>>();                                              // 2
    k_keygemm<<<dim3(X_DIM/128, 7), 128>>>();                         // 3
    k_rred<<<3, 256>>>();                                             // 4
    k_G<<<(K_DIM*U_DIM*H_DIM*81 + 255)/256, 256>>>(a);                // 5
    k_fold<<<(F_DIM*4096 + 255)/256, 256>>>();                        // 6
    k_ksum<<<256, 256>>>();                                           // 7
    k_Z<<<(N_NODES*H_DIM + 255)/256, 256>>>();                        // 8
    k_querygemm<<<dim3(3, N_NODES/128, H_DIM), 128>>>();              // 9
    k_out<<<(N_NODES*9)/32, 256>>>(Wo, out);                          // 10
}

// round 16
// speedup vs baseline: 1.1293x; 1.0243x over previous
#include <cuda_runtime.h>
#include <math.h>

#define N_NODES 2048
#define C_DIM   256
#define H_DIM   8
#define DQK_DIM 32
#define CV_DIM  16
#define K_DIM   8
#define U_DIM   25
#define F_DIM   400           // 2*K*U : cos block then sin block
#define X_DIM   36864         // H * DQK * CV * 9
#define XH_DIM  4608          // per-h slab of X

// ---------------- scratch (static __device__, no allocation) ----------------
__device__ float  d_qfT  [256 * N_NODES];
__device__ float  d_kfT  [256 * N_NODES];
__device__ float  d_vT   [1152 * N_NODES];
__device__ float  d_PhiT [F_DIM * N_NODES];
__device__ float  d_kfsum[256];
__device__ float  d_Z    [N_NODES * H_DIM];
__device__ float  d_Mbuf [(size_t)F_DIM * X_DIM];
__device__ float  d_Bbuf [(size_t)F_DIM * X_DIM];
__device__ float  d_accb [(size_t)N_NODES * 9 * 128];
__device__ float  d_G    [K_DIM * U_DIM * H_DIM * 81];
__device__ float  d_YW   [9 * U_DIM];
__device__ double d_Rs   [729];
__device__ float  d_RRED [729];
__device__ float  d_DIRS [U_DIM * 3];

__device__ __constant__ double c_fact[9] =
    {1.,1.,2.,6.,24.,120.,720.,5040.,40320.};

// ---------------- packed f32x2 helpers ---------------------------------------
__device__ __forceinline__ unsigned long long dup2(float a){
    unsigned long long r;
    asm("mov.b64 %0, {%1, %1};" : "=l"(r) : "f"(a));
    return r;
}
__device__ __forceinline__ void fma2(unsigned long long& d,
                                     unsigned long long a,
                                     unsigned long long b){
    asm("fma.rn.f32x2 %0, %1, %2, %0;" : "+l"(d) : "l"(a), "l"(b));
}
__device__ __forceinline__ float2 unpk(unsigned long long v){
    float2 r;
    asm("mov.b64 {%0, %1}, %2;" : "=f"(r.x), "=f"(r.y) : "l"(v));
    return r;
}

// ---------------- Clebsch-Gordan machinery (fp64, matches numpy) ------------
__device__ double cg_coef(int j1,int m1,int j2,int m2,int j,int m){
    if (m1 + m2 != m) return 0.0;
    int dj = j1 - j2; if (dj < 0) dj = -dj;
    if (j < dj || j > j1 + j2) return 0.0;
    double pref = sqrt((2.0*j+1.0) * c_fact[j+j1-j2] * c_fact[j-j1+j2] *
                       c_fact[j1+j2-j] / c_fact[j1+j2+j+1]);
    pref *= sqrt(c_fact[j+m]*c_fact[j-m]*c_fact[j1-m1]*c_fact[j1+m1]*
                 c_fact[j2-m2]*c_fact[j2+m2]);
    double s = 0.0;
    for (int k = 0; k <= j1 + j2 - j; k++){
        int d1=j1+j2-j-k, d2=j1-m1-k, d3=j2+m2-k, d4=j-j2+m1+k, d5=j-j1-m2+k;
        if (d1 < 0 || d2 < 0 || d3 < 0 || d4 < 0 || d5 < 0) continue;
        double term = 1.0/(c_fact[k]*c_fact[d1]*c_fact[d2]*c_fact[d3]*
                           c_fact[d4]*c_fact[d5]);
        s += (k & 1) ? -term : term;
    }
    return pref * s;
}

__device__ void umat_fill(int l, double* ur, double* ui){
    int n = 2*l + 1;
    for (int i = 0; i < n*n; i++){ ur[i] = 0.0; ui[i] = 0.0; }
    double s = 1.0 / sqrt(2.0);
    for (int m = -l; m <= l; m++){
        if (m > 0){
            ur[(l+m)*n + (l+m)] = (m & 1) ? -s : s;
            ur[(l+m)*n + (l-m)] = s;
        } else if (m == 0){
            ur[l*n + l] = 1.0;
        } else {
            int am = -m;
            ui[(l+m)*n + (l+m)] = s;
            ui[(l+m)*n + (l-m)] = (am & 1) ? s : -s;   // -(-1)^m * s
        }
    }
}

// ---------------- sphere grid + YW + zero d_Rs -------------------------------
__global__ void k_sphere(){
    const double PI = 3.14159265358979323846264338327950288;
    int tid = threadIdx.x;
    for (int i = tid; i < 729; i += blockDim.x) d_Rs[i] = 0.0;
    __shared__ double gx[5], gw[5];
    if (tid == 0){
        double x1 = sqrt(5.0 - 2.0*sqrt(10.0/7.0))/3.0;
        double x2 = sqrt(5.0 + 2.0*sqrt(10.0/7.0))/3.0;
        double w0 = 128.0/225.0;
        double w1 = (322.0 + 13.0*sqrt(70.0))/900.0;
        double w2 = (322.0 - 13.0*sqrt(70.0))/900.0;
        gx[0]=-x2; gx[1]=-x1; gx[2]=0.0; gx[3]=x1; gx[4]=x2;
        gw[0]=w2;  gw[1]=w1;  gw[2]=w0;  gw[3]=w1;  gw[4]=w2;
    }
    __syncthreads();
    if (tid < U_DIM){
        int ith = tid / 5, iph = tid % 5;
        double ct = gx[ith];
        double w  = gw[ith] * (2.0*PI/5.0);
        double ph = 2.0*PI*iph/5.0;
        double st = sqrt(fmax(1.0 - ct*ct, 0.0));
        double x = st*cos(ph), y = st*sin(ph), z = ct;
        d_DIRS[tid*3+0] = (float)x;
        d_DIRS[tid*3+1] = (float)y;
        d_DIRS[tid*3+2] = (float)z;
        double Y[9];
        Y[0]=0.282095; Y[1]=0.488603*y; Y[2]=0.488603*z; Y[3]=0.488603*x;
        Y[4]=1.092548*x*y; Y[5]=1.092548*y*z; Y[6]=0.315392*(3.0*z*z-1.0);
        Y[7]=1.092548*x*z; Y[8]=0.546274*(x*x-y*y);
        for (int e=0;e<9;e++) d_YW[e*U_DIM+tid] = (float)(Y[e]*w);
    }
}

// ---------------- CG: one (l1,l2,L) combo per block --------------------------
__global__ void k_cg(){
    __shared__ double cgc[125], rr[125], ri[125];
    __shared__ double U1r[25],U1i[25],U2r[25],U2i[25],U3r[25],U3i[25];
    __shared__ double nrm[2];
    const int l1s[15] = {0,0,0,1,1,1,1,1,1,2,2,2,2,2,2};
    const int l2s[15] = {0,1,2,0,1,1,1,2,2,0,1,1,2,2,2};
    const int Lss[15] = {0,1,2,1,0,1,2,1,2,2,1,2,0,1,2};
    const int off[3]  = {0,1,4};
    int b = blockIdx.x;
    int l1 = l1s[b], l2 = l2s[b], L = Lss[b];
    int tid = threadIdx.x;
    int n1 = 2*l1+1, n2 = 2*l2+1, n3 = 2*L+1;
    int tot = n1*n2*n3;
    for (int i=tid;i<tot;i+=blockDim.x){
        int i1=i/(n2*n3), i2=(i/n3)%n2, i3=i%n3;
        cgc[i] = cg_coef(l1, i1-l1, l2, i2-l2, L, i3-L);
    }
    if (tid==0){
        umat_fill(l1,U1r,U1i); umat_fill(l2,U2r,U2i); umat_fill(L,U3r,U3i);
        nrm[0]=0.0; nrm[1]=0.0;
    }
    __syncthreads();
    for (int i=tid;i<tot;i+=blockDim.x){
        int a=i/(n2*n3), bb=(i/n3)%n2, c=i%n3;
        double sr=0.0, si=0.0;
        for (int u=0;u<n1;u++)
        for (int v=0;v<n2;v++)
        for (int w=0;w<n3;w++){
            double cg = cgc[(u*n2+v)*n3+w];
            if (cg == 0.0) continue;
            double ar=U1r[a*n1+u], ai=U1i[a*n1+u];
            double br=U2r[bb*n2+v], bi=U2i[bb*n2+v];
            double cr=U3r[c*n3+w], ci=-U3i[c*n3+w];
            double pr=ar*br-ai*bi, pi=ar*bi+ai*br;
            sr += (pr*cr - pi*ci)*cg;
            si += (pr*ci + pi*cr)*cg;
        }
        rr[i]=sr; ri[i]=si;
        atomicAdd(&nrm[0], sr*sr);
        atomicAdd(&nrm[1], si*si);
    }
    __syncthreads();
    bool useRe = (nrm[0] >= nrm[1]);
    for (int i=tid;i<tot;i+=blockDim.x){
        int a=i/(n2*n3), bb=(i/n3)%n2, c=i%n3;
        double val = useRe ? rr[i] : ri[i];
        d_Rs[(off[l1]+a)*81 + (off[l2]+bb)*9 + (off[L]+c)] = val;
    }
}

// ---------------- RRED finalize ----------------------------------------------
__global__ void k_rred(){
    int i = blockIdx.x*blockDim.x + threadIdx.x;
    if (i >= 729) return;
    int m = i % 9;
    double cnt = (m==0) ? 3.0 : 6.0;
    d_RRED[i] = (float)(d_Rs[i]/cnt);
}

// ---------------- G[k,u,h,l,m] = sum_e YW[e,u]*a[ldeg(e),h,k]*RRED[e,l,m] ----
__global__ void k_G(const float* __restrict__ a){
    int idx = blockIdx.x*blockDim.x + threadIdx.x;
    if (idx >= K_DIM*U_DIM*H_DIM*81) return;
    int m = idx % 9, l = (idx/9)%9, h = (idx/81)%8, u = (idx/648)%25, k = idx/16200;
    const int ldeg[9] = {0,1,1,1,2,2,2,2,2};
    float s = 0.f;
    #pragma unroll
    for (int e=0;e<9;e++)
        s += d_YW[e*25+u] * a[ldeg[e]*64 + h*8 + k] * d_RRED[e*81 + l*9 + m];
    d_G[idx] = s;
}

// ---------------- per-node features (2 nodes / block) ------------------------
#define NPB 2
__global__ void k_features(const float* __restrict__ pos,
                           const float* __restrict__ feat,
                           const float* __restrict__ Wq,
                           const float* __restrict__ Wk,
                           const float* __restrict__ Wv,
                           const float* __restrict__ kappa){
    __shared__ float sf  [NPB][2304];
    __shared__ float s123[NPB][768];
    __shared__ float spos[NPB][3];
    __shared__ float skap[8];
    int tid = threadIdx.x;
    int n0  = blockIdx.x * NPB;
    if (tid < NPB*3) spos[tid/3][tid%3] = pos[n0*3 + tid];
    if (tid < 8) skap[tid] = kappa[tid];
    for (int nb=0; nb<NPB; nb++)
        for (int i=tid; i<2304; i+=256)
            sf[nb][i] = feat[(size_t)(n0+nb)*2304 + i];
    __syncthreads();
    for (int i=tid; i<NPB*256; i+=256){
        int nb = i/256, c = i%256;
        const float* f = sf[nb];
        s123[nb][c] = f[c];
        s123[nb][256+c] = sqrtf(f[256+c]*f[256+c] + f[512+c]*f[512+c] +
                                f[768+c]*f[768+c] + 1e-8f);
        float s = 1e-8f;
        #pragma unroll
        for (int m=4;m<9;m++){ float t = f[m*256+c]; s += t*t; }
        s123[nb][512+c] = sqrtf(s);
    }
    __syncthreads();

    // q,k projections: thread = output column j (0..255)
    {
        float qa[NPB] = {0,0}, ka[NPB] = {0,0};
        int j = tid;
        for (int g=0; g<3; g++){
            const float* wqb = Wq + g*65536 + j;
            const float* wkb = Wk + g*65536 + j;
            #pragma unroll 4
            for (int c=0;c<256;c++){
                float wq = wqb[c*256];
                float wk = wkb[c*256];
                #pragma unroll
                for (int nb=0;nb<NPB;nb++){
                    float s = s123[nb][g*256+c];
                    qa[nb] += s*wq; ka[nb] += s*wk;
                }
            }
        }
        #pragma unroll
        for (int nb=0;nb<NPB;nb++){
            int n = n0+nb;
            float q = qa[nb], k = ka[nb];
            float qf = (q > 0.f) ? q + 1.f : expf(q);
            float kf = (k > 0.f) ? k + 1.f : expf(k);
            d_qfT[(size_t)j*N_NODES + n] = qf;
            d_kfT[(size_t)j*N_NODES + n] = kf;
        }
    }

    // v: jv = h*16+c (0..127), one node per half-block
    {
        int jv = tid & 127, nb = tid >> 7;
        float acc[9];
        #pragma unroll
        for (int l=0;l<9;l++) acc[l] = 0.f;
        #pragma unroll 4
        for (int ch=0; ch<256; ch++){
            float w = Wv[ch*128 + jv];
            #pragma unroll
            for (int l=0;l<9;l++) acc[l] += sf[nb][l*256+ch]*w;
        }
        #pragma unroll
        for (int l=0;l<9;l++)
            d_vT[(size_t)(jv*9+l)*N_NODES + (n0+nb)] = acc[l];
    }

    // Phi
    for (int i=tid; i<NPB*200; i+=256){
        int nb = i/200, r = i%200;
        int k = r/25, u = r%25;
        float dot = spos[nb][0]*d_DIRS[u*3+0] + spos[nb][1]*d_DIRS[u*3+1] +
                    spos[nb][2]*d_DIRS[u*3+2];
        float ph = skap[k]*dot;
        float c, s;
        sincosf(ph, &s, &c);
        d_PhiT[(size_t)r      *N_NODES + n0+nb] = c;
        d_PhiT[(size_t)(200+r)*N_NODES + n0+nb] = s;
    }
}

// ---------------- kfsum + Z --------------------------------------------------
__global__ void k_ksum(){
    int j = blockIdx.x;
    int tid = threadIdx.x;
    float s = 0.f;
    for (int n=tid; n<N_NODES; n+=256) s += d_kfT[(size_t)j*N_NODES + n];
    #pragma unroll
    for (int o=16;o;o>>=1) s += __shfl_xor_sync(0xffffffffu, s, o);
    __shared__ float red[8];
    if ((tid & 31) == 0) red[tid>>5] = s;
    __syncthreads();
    if (tid == 0){
        float t = 0.f;
        #pragma unroll
        for (int w=0;w<8;w++) t += red[w];
        d_kfsum[j] = t;
    }
}

__global__ void k_Z(){
    int idx = blockIdx.x*blockDim.x + threadIdx.x;
    if (idx >= N_NODES*H_DIM) return;
    int n = idx % N_NODES, h = idx / N_NODES;
    float s = 0.f;
    #pragma unroll
    for (int d=0; d<32; d++)
        s += d_qfT[(size_t)(h*32+d)*N_NODES + n] * d_kfsum[h*32+d];
    d_Z[idx] = s + 1e-6f;
}

// ---------------- key GEMM: M[f,x] = sum_n Phi[f,n]*kf[hd(x),n]*v[hcl(x),n] --
// R6 champion kernel, K-chunk 16 (proven optimum), unchanged
#define KG_AST 68
#define KG_BST 132
__global__ void __launch_bounds__(128,3) k_keygemm(){
    __shared__ float As[16*KG_AST];
    __shared__ float Bs[16*KG_BST];
    int tid = threadIdx.x;
    int x0 = blockIdx.x * 128;
    int f0 = blockIdx.y * 64;
    int wid = tid>>5, lane = tid&31;
    int wf = wid>>1, wx = wid&1;      // warp grid 2f x 2x
    int tf = lane&3, tx = lane>>2;    // thread grid 4f x 8x
    int fr = tid&15, fcg = tid>>4;    // fill: n-row 0..15, col group 0..7

    unsigned kfo[16], vo[16];
    #pragma unroll
    for (int q=0;q<16;q++){
        int x = x0 + fcg + q*8;
        int h = x / XH_DIM, rem = x - h*XH_DIM;
        int d = rem / 144, cl = rem - d*144;
        kfo[q] = (unsigned)(h*32+d)*N_NODES;
        vo[q]  = (unsigned)(h*144+cl)*N_NODES;
    }
    unsigned long long acc[8][4];
    #pragma unroll
    for (int i=0;i<8;i++)
        #pragma unroll
        for (int j=0;j<4;j++) acc[i][j] = 0ull;

    for (int nb=0; nb<N_NODES; nb+=16){
        #pragma unroll
        for (int q=0;q<8;q++){
            int col = fcg + q*8;
            int f = f0 + col;
            As[fr*KG_AST + col] = (f < F_DIM) ? d_PhiT[(size_t)f*N_NODES + nb + fr] : 0.f;
        }
        #pragma unroll
        for (int q=0;q<16;q++){
            int col = fcg + q*8;
            Bs[fr*KG_BST + col] = d_kfT[kfo[q] + nb + fr] * d_vT[vo[q] + nb + fr];
        }
        __syncthreads();
        #pragma unroll
        for (int kk=0;kk<16;kk++){
            const float* ar = &As[kk*KG_AST + wf*32 + tf*8];
            float4 a0 = *(const float4*)ar;
            float4 a1 = *(const float4*)(ar+4);
            unsigned long long ad[8];
            ad[0]=dup2(a0.x); ad[1]=dup2(a0.y); ad[2]=dup2(a0.z); ad[3]=dup2(a0.w);
            ad[4]=dup2(a1.x); ad[5]=dup2(a1.y); ad[6]=dup2(a1.z); ad[7]=dup2(a1.w);
            const float* br = &Bs[kk*KG_BST + wx*64 + tx*8];
            ulonglong2 b01 = *(const ulonglong2*)br;
            ulonglong2 b23 = *(const ulonglong2*)(br+4);
            #pragma unroll
            for (int i=0;i<8;i++){
                fma2(acc[i][0], ad[i], b01.x);
                fma2(acc[i][1], ad[i], b01.y);
                fma2(acc[i][2], ad[i], b23.x);
                fma2(acc[i][3], ad[i], b23.y);
            }
        }
        __syncthreads();
    }
    #pragma unroll
    for (int i=0;i<8;i++){
        int f = f0 + wf*32 + tf*8 + i;
        if (f >= F_DIM) continue;
        float* mrow = d_Mbuf + (size_t)f*X_DIM + x0 + wx*64 + tx*8;
        ulonglong2 s0; s0.x = acc[i][0]; s0.y = acc[i][1];
        ulonglong2 s1; s1.x = acc[i][2]; s1.y = acc[i][3];
        *(ulonglong2*)&mrow[0] = s0;
        *(ulonglong2*)&mrow[4] = s1;
    }
}

// ---------------- fold: B[f,h,d,c,m] = sum_l M[f,h,d,c,l]*G[k,u,h,l,m] -------
__global__ void k_fold(){
    int idx = blockIdx.x*blockDim.x + threadIdx.x;
    if (idx >= F_DIM*4096) return;
    int c = idx % 16, d = (idx/16)%32, h = (idx/512)%8, f = idx/4096;
    int k = (f % 200) / 25, u = f % 25;
    const float* g = d_G + (size_t)((k*25+u)*8 + h)*81;
    size_t base = (size_t)f*X_DIM + h*XH_DIM + d*144 + c*9;
    float mrow[9];
    #pragma unroll
    for (int l=0;l<9;l++) mrow[l] = d_Mbuf[base+l];
    #pragma unroll
    for (int m=0;m<9;m++){
        float s = 0.f;
        #pragma unroll
        for (int l=0;l<9;l++) s += mrow[l]*g[l*9+m];
        d_Bbuf[base+m] = s;
    }
}

// ---------------- query GEMM: acc[n,cm] = sum_{f,d} Phi*qf*B ------------------
// R15 version: K-chunk 32 (merged hb halves, barriers halved), R6 inner body
#define QG_AST 132
#define QG_BST 50
__global__ void __launch_bounds__(128,3) k_querygemm(){
    __shared__ float As[32*QG_AST];
    __shared__ float Bs[32*QG_BST];
    int tid = threadIdx.x;
    int cm0 = blockIdx.x * 48;
    int n0  = blockIdx.y * 128;
    int h   = blockIdx.z;
    int wid = tid>>5, lane = tid&31;
    int wn = wid>>1, wc = wid&1;      // warp grid 2n x 2cm
    int tn = lane>>2, tx = lane&3;    // thread grid 8n x 4cm

    float qreg[32];
    #pragma unroll
    for (int d=0;d<32;d++)
        qreg[d] = d_qfT[(size_t)(h*32+d)*N_NODES + n0 + tid];

    unsigned long long acc[4][6];
    #pragma unroll
    for (int i=0;i<4;i++)
        #pragma unroll
        for (int j=0;j<6;j++) acc[i][j] = 0ull;

    for (int f=0; f<F_DIM; f++){
        float ph = d_PhiT[(size_t)f*N_NODES + n0 + tid];
        const float* bb = d_Bbuf + (size_t)f*X_DIM + h*XH_DIM + cm0;
        #pragma unroll
        for (int dl=0; dl<32; dl++)
            As[dl*QG_AST + tid] = ph * qreg[dl];
        #pragma unroll
        for (int j=0;j<12;j++){
            int idx = tid + j*128;
            int r = idx/48, c = idx - r*48;
            Bs[r*QG_BST + c] = bb[r*144 + c];
        }
        __syncthreads();
        #pragma unroll
        for (int kk=0;kk<32;kk++){
            const float* ar = &As[kk*QG_AST + wn*64 + tn*8];
            ulonglong2 a01 = *(const ulonglong2*)ar;
            ulonglong2 a23 = *(const ulonglong2*)(ar+4);
            unsigned long long ra[4] = {a01.x, a01.y, a23.x, a23.y};
            const float* br = &Bs[kk*QG_BST + wc*24 + tx*6];
            float2 p0 = *(const float2*)br;
            float2 p1 = *(const float2*)(br+2);
            float2 p2 = *(const float2*)(br+4);
            unsigned long long bd[6];
            bd[0]=dup2(p0.x); bd[1]=dup2(p0.y); bd[2]=dup2(p1.x);
            bd[3]=dup2(p1.y); bd[4]=dup2(p2.x); bd[5]=dup2(p2.y);
            #pragma unroll
            for (int i=0;i<4;i++)
                #pragma unroll
                for (int j=0;j<6;j++)
                    fma2(acc[i][j], ra[i], bd[j]);
        }
        __syncthreads();
    }
    #pragma unroll
    for (int i=0;i<4;i++){
        int nA = n0 + wn*64 + tn*8 + i*2;
        float z0 = 1.f / d_Z[h*N_NODES + nA];
        float z1 = 1.f / d_Z[h*N_NODES + nA + 1];
        #pragma unroll
        for (int j=0;j<6;j++){
            float2 v = unpk(acc[i][j]);
            int cm = cm0 + wc*24 + tx*6 + j;
            int c = cm / 9, m = cm - (cm/9)*9;
            d_accb[((size_t)nA*9     + m)*128 + h*16 + c] = v.x * z0;
            d_accb[((size_t)(nA+1)*9 + m)*128 + h*16 + c] = v.y * z1;
        }
    }
}

// ---------------- output GEMM: out[row,:] = accb[row,:] @ Wo ----------------
__global__ void __launch_bounds__(256) k_out(const float* __restrict__ Wo,
                                             float* __restrict__ out){
    __shared__ float Ash[32][128];
    int tid = threadIdx.x;
    int r0 = blockIdx.x * 32;
    for (int i=tid; i<32*128; i+=256)
        Ash[i/128][i%128] = d_accb[(size_t)(r0 + i/128)*128 + (i%128)];
    __syncthreads();
    float acc[32];
    #pragma unroll
    for (int r=0;r<32;r++) acc[r] = 0.f;
    for (int j=0;j<128;j++){
        float w = Wo[j*256 + tid];
        #pragma unroll
        for (int r=0;r<32;r++) acc[r] += Ash[r][j]*w;
    }
    #pragma unroll
    for (int r=0;r<32;r++)
        out[(size_t)(r0+r)*256 + tid] = acc[r];
}

// ---------------- launch -----------------------------------------------------
extern "C" void kernel_launch(void* const* d_in, const int* in_sizes, int n_in,
                              void* d_out, int out_size){
    const float* pos   = (const float*)d_in[0];
    const float* feat  = (const float*)d_in[1];
    const float* Wq    = (const float*)d_in[2];
    const float* Wk    = (const float*)d_in[3];
    const float* Wv    = (const float*)d_in[4];
    const float* Wo    = (const float*)d_in[5];
    const float* a     = (const float*)d_in[6];
    const float* kappa = (const float*)d_in[7];
    float* out = (float*)d_out;

    // order chosen so ncu's captured slot lands on k_keygemm
    k_sphere<<<1, 128>>>();                                           // 0
    k_features<<<N_NODES/NPB, 256>>>(pos, feat, Wq, Wk, Wv, kappa);   // 1
    k_cg<<<15, 128>>>();                                              // 2
    k_keygemm<<<dim3(X_DIM/128, 7), 128>>>();                         // 3
    k_rred<<<3, 256>>>();                                             // 4
    k_G<<<(K_DIM*U_DIM*H_DIM*81 + 255)/256, 256>>>(a);                // 5
    k_fold<<<(F_DIM*4096 + 255)/256, 256>>>();                        // 6
    k_ksum<<<256, 256>>>();                                           // 7
    k_Z<<<(N_NODES*H_DIM + 255)/256, 256>>>();                        // 8
    k_querygemm<<<dim3(3, N_NODES/128, H_DIM), 128>>>();              // 9
    k_out<<<(N_NODES*9)/32, 256>>>(Wo, out);                          // 10
}